// round 5
// baseline (speedup 1.0000x reference)
#include <cuda_runtime.h>
#include <math.h>

#define B_   2
#define T_   1024
#define C_   1024
#define NH   16
#define NKV  4
#define HD   64
#define S_   2048
#define ROWS 2048
#define KVW  (NKV*HD)

// ---------------- scratch ----------------
__device__ float g_q [ROWS * C_];
__device__ float g_ao[ROWS * C_];
__device__ float g_invf[32];
__device__ float g_cos[ROWS * 32];
__device__ float g_sin[ROWS * 32];

// ---------------- helpers ----------------
__device__ __forceinline__ unsigned f2tf(float x) {
    unsigned u;
    asm("cvt.rna.tf32.f32 %0, %1;" : "=r"(u) : "f"(x));
    return u;
}
__device__ __forceinline__ void mma_tf32(float* c,
                                         unsigned a0, unsigned a1, unsigned a2, unsigned a3,
                                         unsigned b0, unsigned b1) {
    asm volatile(
        "mma.sync.aligned.m16n8k8.row.col.f32.tf32.tf32.f32 "
        "{%0,%1,%2,%3}, {%4,%5,%6,%7}, {%8,%9}, {%0,%1,%2,%3};"
        : "+f"(c[0]), "+f"(c[1]), "+f"(c[2]), "+f"(c[3])
        : "r"(a0), "r"(a1), "r"(a2), "r"(a3), "r"(b0), "r"(b1));
}
__device__ __forceinline__ void cpa16(unsigned s, const float* g) {
    asm volatile("cp.async.ca.shared.global [%0], [%1], 16;" :: "r"(s), "l"(g));
}
__device__ __forceinline__ void cpa_commit() { asm volatile("cp.async.commit_group;"); }

// ---------------- GEMM core: 128M x 64N tile, 128 threads, K=1024, cp.async x2 ----------------
#define AS 36
#define BS 72
#define GSM ((2*128*AS + 2*32*BS) * 4)   // 55296 B

__device__ __forceinline__ void gemm_main(const float* __restrict__ A,
                                          const float* __restrict__ Bw,
                                          int ldB, int m0, int n0,
                                          float acc[2][8][4], float* smf) {
    float* A_s = smf;
    float* B_s = smf + 2 * 128 * AS;
    const int tid = threadIdx.x;
    unsigned aBase = (unsigned)__cvta_generic_to_shared(A_s);
    unsigned bBase = (unsigned)__cvta_generic_to_shared(B_s);

    const int arow = tid >> 3, ac4 = (tid & 7) << 2;
    const int brow = tid >> 4, bc4 = (tid & 15) << 2;

    #pragma unroll
    for (int i = 0; i < 8; i++)
        cpa16(aBase + (((arow + i * 16) * AS + ac4) << 2),
              &A[(size_t)(m0 + arow + i * 16) * 1024 + ac4]);
    #pragma unroll
    for (int i = 0; i < 4; i++)
        cpa16(bBase + (((brow + i * 8) * BS + bc4) << 2),
              &Bw[(size_t)(brow + i * 8) * ldB + n0 + bc4]);
    cpa_commit();

    const int lane = tid & 31, warp = tid >> 5;
    const int tq = lane >> 2, tr = lane & 3;
    int buf = 0;
    for (int c = 0; c < 32; c++) {
        if (c < 31) {
            int kc = (c + 1) * 32;
            int nb = buf ^ 1;
            #pragma unroll
            for (int i = 0; i < 8; i++)
                cpa16(aBase + ((((nb * 128) + arow + i * 16) * AS + ac4) << 2),
                      &A[(size_t)(m0 + arow + i * 16) * 1024 + kc + ac4]);
            #pragma unroll
            for (int i = 0; i < 4; i++)
                cpa16(bBase + ((((nb * 32) + brow + i * 8) * BS + bc4) << 2),
                      &Bw[(size_t)(kc + brow + i * 8) * ldB + n0 + bc4]);
            cpa_commit();
            asm volatile("cp.async.wait_group 1;");
        } else {
            asm volatile("cp.async.wait_group 0;");
        }
        __syncthreads();

        const float* Ab = A_s + buf * 128 * AS;
        const float* Bb = B_s + buf * 32 * BS;
        #pragma unroll
        for (int ks = 0; ks < 4; ks++) {
            unsigned a[2][4];
            #pragma unroll
            for (int mt = 0; mt < 2; mt++) {
                const float* p = &Ab[(warp * 32 + mt * 16 + tq) * AS + ks * 8 + tr];
                a[mt][0] = f2tf(p[0]);
                a[mt][1] = f2tf(p[8 * AS]);
                a[mt][2] = f2tf(p[4]);
                a[mt][3] = f2tf(p[8 * AS + 4]);
            }
            #pragma unroll
            for (int nt = 0; nt < 8; nt++) {
                unsigned b0 = f2tf(Bb[(ks * 8 + tr) * BS + nt * 8 + tq]);
                unsigned b1 = f2tf(Bb[(ks * 8 + tr + 4) * BS + nt * 8 + tq]);
                mma_tf32(acc[0][nt], a[0][0], a[0][1], a[0][2], a[0][3], b0, b1);
                mma_tf32(acc[1][nt], a[1][0], a[1][1], a[1][2], a[1][3], b0, b1);
            }
        }
        __syncthreads();
        buf ^= 1;
    }
}

// rope rotate in registers: pairs (nt, nt+4)
__device__ __forceinline__ void rope_acc(float acc[2][8][4], int m0) {
    const int lane = threadIdx.x & 31, warp = threadIdx.x >> 5;
    const int tq = lane >> 2, tr = lane & 3;
    #pragma unroll
    for (int mt = 0; mt < 2; mt++) {
        int r0 = m0 + warp * 32 + mt * 16 + tq;
        int r1 = r0 + 8;
        #pragma unroll
        for (int nt = 0; nt < 4; nt++) {
            int i0 = nt * 8 + 2 * tr;
            float2 c0 = *(const float2*)&g_cos[r0 * 32 + i0];
            float2 s0 = *(const float2*)&g_sin[r0 * 32 + i0];
            float2 c1 = *(const float2*)&g_cos[r1 * 32 + i0];
            float2 s1 = *(const float2*)&g_sin[r1 * 32 + i0];
            float x1, x2;
            x1 = acc[mt][nt][0]; x2 = acc[mt][nt + 4][0];
            acc[mt][nt][0] = x1 * c0.x - x2 * s0.x;  acc[mt][nt + 4][0] = x2 * c0.x + x1 * s0.x;
            x1 = acc[mt][nt][1]; x2 = acc[mt][nt + 4][1];
            acc[mt][nt][1] = x1 * c0.y - x2 * s0.y;  acc[mt][nt + 4][1] = x2 * c0.y + x1 * s0.y;
            x1 = acc[mt][nt][2]; x2 = acc[mt][nt + 4][2];
            acc[mt][nt][2] = x1 * c1.x - x2 * s1.x;  acc[mt][nt + 4][2] = x2 * c1.x + x1 * s1.x;
            x1 = acc[mt][nt][3]; x2 = acc[mt][nt + 4][3];
            acc[mt][nt][3] = x1 * c1.y - x2 * s1.y;  acc[mt][nt + 4][3] = x2 * c1.y + x1 * s1.y;
        }
    }
}

// ---------------- merged QKV projection (+rope, +scatter) ----------------
__global__ __launch_bounds__(128, 4) void qkv_gemm(const float* __restrict__ x,
                                                   const float* __restrict__ Wq,
                                                   const float* __restrict__ Wk,
                                                   const float* __restrict__ Wv,
                                                   float* __restrict__ kout,
                                                   float* __restrict__ vout) {
    extern __shared__ float smf[];
    const int bx = blockIdx.x, m0 = blockIdx.y * 128;
    const float* Bw; int ldB, n0, mode;
    if (bx < 16)      { Bw = Wq; ldB = 1024; n0 = bx * 64;        mode = 0; }
    else if (bx < 20) { Bw = Wk; ldB = 256;  n0 = (bx - 16) * 64; mode = 1; }
    else              { Bw = Wv; ldB = 256;  n0 = (bx - 20) * 64; mode = 2; }

    float acc[2][8][4];
    #pragma unroll
    for (int i = 0; i < 2; i++)
        #pragma unroll
        for (int j = 0; j < 8; j++)
            #pragma unroll
            for (int k = 0; k < 4; k++) acc[i][j][k] = 0.f;

    gemm_main(x, Bw, ldB, m0, n0, acc, smf);

    if (mode != 2) rope_acc(acc, m0);

    const int lane = threadIdx.x & 31, warp = threadIdx.x >> 5;
    const int tq = lane >> 2, tr = lane & 3;
    #pragma unroll
    for (int mt = 0; mt < 2; mt++) {
        int r = m0 + warp * 32 + mt * 16 + tq;
        if (mode == 0) {
            float* p0 = &g_q[(size_t)r * C_ + n0];
            float* p1 = &g_q[(size_t)(r + 8) * C_ + n0];
            #pragma unroll
            for (int nt = 0; nt < 8; nt++) {
                *(float2*)&p0[nt * 8 + 2 * tr] = make_float2(acc[mt][nt][0], acc[mt][nt][1]);
                *(float2*)&p1[nt * 8 + 2 * tr] = make_float2(acc[mt][nt][2], acc[mt][nt][3]);
            }
        } else {
            int b = r >> 10, t = r & 1023;
            int kv = (mode == 1) ? (bx - 16) : (bx - 20);
            float* dst = (mode == 1) ? kout : vout;
            float* p0 = &dst[(size_t)((b * NKV + kv) * S_ + 1024 + t) * HD];
            float* p1 = &dst[(size_t)((b * NKV + kv) * S_ + 1024 + t + 8) * HD];
            #pragma unroll
            for (int nt = 0; nt < 8; nt++) {
                *(float2*)&p0[nt * 8 + 2 * tr] = make_float2(acc[mt][nt][0], acc[mt][nt][1]);
                *(float2*)&p1[nt * 8 + 2 * tr] = make_float2(acc[mt][nt][2], acc[mt][nt][3]);
            }
        }
    }
}

// ---------------- O projection ----------------
__global__ __launch_bounds__(128, 4) void o_gemm(const float* __restrict__ A,
                                                 const float* __restrict__ Wo,
                                                 float* __restrict__ out) {
    extern __shared__ float smf[];
    const int m0 = blockIdx.y * 128, n0 = blockIdx.x * 64;
    float acc[2][8][4];
    #pragma unroll
    for (int i = 0; i < 2; i++)
        #pragma unroll
        for (int j = 0; j < 8; j++)
            #pragma unroll
            for (int k = 0; k < 4; k++) acc[i][j][k] = 0.f;

    gemm_main(A, Wo, 1024, m0, n0, acc, smf);

    const int lane = threadIdx.x & 31, warp = threadIdx.x >> 5;
    const int tq = lane >> 2, tr = lane & 3;
    #pragma unroll
    for (int mt = 0; mt < 2; mt++) {
        int r = m0 + warp * 32 + mt * 16 + tq;
        float* p0 = &out[(size_t)r * C_ + n0];
        float* p1 = &out[(size_t)(r + 8) * C_ + n0];
        #pragma unroll
        for (int nt = 0; nt < 8; nt++) {
            *(float2*)&p0[nt * 8 + 2 * tr] = make_float2(acc[mt][nt][0], acc[mt][nt][1]);
            *(float2*)&p1[nt * 8 + 2 * tr] = make_float2(acc[mt][nt][2], acc[mt][nt][3]);
        }
    }
}

// ---------------- tables ----------------
__global__ void invf_init() {
    if (threadIdx.x < 32)
        g_invf[threadIdx.x] = (float)pow(10000.0, -(double)threadIdx.x / 32.0);
}
__global__ void rope_tab(const int* __restrict__ pidx) {
    int idx = blockIdx.x * blockDim.x + threadIdx.x;
    if (idx >= ROWS * 32) return;
    int i = idx & 31, row = idx >> 5;
    int p = min(max(pidx[row] + (row & 1023) + 1024, 0), 4095);
    float ang = (float)p * g_invf[i];
    float c, s;
    sincosf(ang, &s, &c);
    g_cos[idx] = c;
    g_sin[idx] = s;
}

// ---------------- cache halves copy ----------------
__global__ void copy_cache(const float* __restrict__ kc, const float* __restrict__ vc,
                           float* __restrict__ kout, float* __restrict__ vout) {
    int idx = blockIdx.x * blockDim.x + threadIdx.x;
    if (idx >= B_ * NKV * 1024 * 16) return;
    int d4 = idx & 15;
    int s  = (idx >> 4) & 1023;
    int bk = idx >> 14;
    int dst = ((bk * S_) + s) * 16 + d4;
    ((float4*)kout)[dst] = ((const float4*)kc)[idx];
    ((float4*)vout)[dst] = ((const float4*)vc)[idx];
}

// ---------------- Flash attention v5: permuted layouts, LDS.128 fragment loads ----------------
// Kp[d][perm(key)], Vp[k][perm(d)], perm(i) = (i&7)*8 + (i>>3).  Row stride 68 floats.
#define KP 68
#define ASM ((2 * 64 * KP) * 4)   // 34816 B

__global__ __launch_bounds__(256, 2) void attn_k(const float* __restrict__ kall,
                                                 const float* __restrict__ vall) {
    extern __shared__ unsigned sm[];
    unsigned* Kp = sm;             // [64 d][KP]
    unsigned* Vp = sm + 64 * KP;   // [64 k][KP]

    const int tid = threadIdx.x, lane = tid & 31, warp = tid >> 5;
    const int tq = lane >> 2, tr = lane & 3;
    const int qt = blockIdx.x, h = blockIdx.y, b = blockIdx.z;
    const float* kb = kall + (size_t)(b * NKV + (h >> 2)) * S_ * HD;
    const float* vb = vall + (size_t)(b * NKV + (h >> 2)) * S_ * HD;
    const int qrow = qt * 128 + warp * 16;

    // Q fragments (scale folded), registers for the whole kernel
    unsigned qa[8][4];
    const float* qp = g_q + (size_t)(b * T_ + qrow) * C_ + h * HD;
    #pragma unroll
    for (int ks = 0; ks < 8; ks++) {
        qa[ks][0] = f2tf(qp[(size_t)tq * C_ + ks * 8 + tr] * 0.125f);
        qa[ks][1] = f2tf(qp[(size_t)(tq + 8) * C_ + ks * 8 + tr] * 0.125f);
        qa[ks][2] = f2tf(qp[(size_t)tq * C_ + ks * 8 + tr + 4] * 0.125f);
        qa[ks][3] = f2tf(qp[(size_t)(tq + 8) * C_ + ks * 8 + tr + 4] * 0.125f);
    }

    float m0 = -1e30f, m1 = -1e30f, l0 = 0.f, l1 = 0.f;
    float o[8][4];
    #pragma unroll
    for (int nt = 0; nt < 8; nt++)
        #pragma unroll
        for (int k = 0; k < 4; k++) o[nt][k] = 0.f;

    const int srcA = (lane & 28) | ((lane >> 1) & 1);
    const int srcB = srcA + 2;
    const bool eo = lane & 1;

    // fill index precompute
    const int fk  = tid & 63;           // K fill: key row (k-strided LDG, 2-way STS)
    const int kcol = ((fk & 7) << 3) | (fk >> 3);

    for (int c0 = 0; c0 < S_; c0 += 64) {
        __syncthreads();
        // ---- fill Kp (permuted key) and Vp (permuted d) ----
        #pragma unroll
        for (int p = 0; p < 4; p++) {
            int c = tid + p * 256;
            // K: thread owns (key=fk, j = c>>6)
            int j = c >> 6;
            float4 kq = *(const float4*)&kb[(size_t)(c0 + fk) * HD + 4 * j];
            Kp[(4 * j + 0) * KP + kcol] = f2tf(kq.x);
            Kp[(4 * j + 1) * KP + kcol] = f2tf(kq.y);
            Kp[(4 * j + 2) * KP + kcol] = f2tf(kq.z);
            Kp[(4 * j + 3) * KP + kcol] = f2tf(kq.w);
            // V: coalesced (k = c>>4, j = c&15)
            int vk = c >> 4, vj = c & 15;
            float4 vq = *(const float4*)&vb[(size_t)(c0 + vk) * HD + 4 * vj];
            int d0 = 4 * vj;
            Vp[vk * KP + (((d0 + 0) & 7) << 3) + ((d0 + 0) >> 3)] = f2tf(vq.x);
            Vp[vk * KP + (((d0 + 1) & 7) << 3) + ((d0 + 1) >> 3)] = f2tf(vq.y);
            Vp[vk * KP + (((d0 + 2) & 7) << 3) + ((d0 + 2) >> 3)] = f2tf(vq.z);
            Vp[vk * KP + (((d0 + 3) & 7) << 3) + ((d0 + 3) >> 3)] = f2tf(vq.w);
        }
        __syncthreads();

        // ---- S = Q @ K^T : B-fragments via LDS.128 ----
        float s[8][4];
        #pragma unroll
        for (int nt = 0; nt < 8; nt++)
            #pragma unroll
            for (int k = 0; k < 4; k++) s[nt][k] = 0.f;
        #pragma unroll
        for (int ks = 0; ks < 8; ks++) {
            uint4 b0a = *(const uint4*)&Kp[(ks * 8 + tr) * KP + tq * 8];
            uint4 b0b = *(const uint4*)&Kp[(ks * 8 + tr) * KP + tq * 8 + 4];
            uint4 b1a = *(const uint4*)&Kp[(ks * 8 + tr + 4) * KP + tq * 8];
            uint4 b1b = *(const uint4*)&Kp[(ks * 8 + tr + 4) * KP + tq * 8 + 4];
            mma_tf32(s[0], qa[ks][0], qa[ks][1], qa[ks][2], qa[ks][3], b0a.x, b1a.x);
            mma_tf32(s[1], qa[ks][0], qa[ks][1], qa[ks][2], qa[ks][3], b0a.y, b1a.y);
            mma_tf32(s[2], qa[ks][0], qa[ks][1], qa[ks][2], qa[ks][3], b0a.z, b1a.z);
            mma_tf32(s[3], qa[ks][0], qa[ks][1], qa[ks][2], qa[ks][3], b0a.w, b1a.w);
            mma_tf32(s[4], qa[ks][0], qa[ks][1], qa[ks][2], qa[ks][3], b0b.x, b1b.x);
            mma_tf32(s[5], qa[ks][0], qa[ks][1], qa[ks][2], qa[ks][3], b0b.y, b1b.y);
            mma_tf32(s[6], qa[ks][0], qa[ks][1], qa[ks][2], qa[ks][3], b0b.z, b1b.z);
            mma_tf32(s[7], qa[ks][0], qa[ks][1], qa[ks][2], qa[ks][3], b0b.w, b1b.w);
        }

        // ---- online softmax ----
        float mx0 = -1e30f, mx1 = -1e30f;
        #pragma unroll
        for (int nt = 0; nt < 8; nt++) {
            mx0 = fmaxf(mx0, fmaxf(s[nt][0], s[nt][1]));
            mx1 = fmaxf(mx1, fmaxf(s[nt][2], s[nt][3]));
        }
        mx0 = fmaxf(mx0, __shfl_xor_sync(0xffffffffu, mx0, 1));
        mx0 = fmaxf(mx0, __shfl_xor_sync(0xffffffffu, mx0, 2));
        mx1 = fmaxf(mx1, __shfl_xor_sync(0xffffffffu, mx1, 1));
        mx1 = fmaxf(mx1, __shfl_xor_sync(0xffffffffu, mx1, 2));
        float nm0 = fmaxf(m0, mx0), nm1 = fmaxf(m1, mx1);
        float al0 = __expf(m0 - nm0), al1 = __expf(m1 - nm1);
        m0 = nm0; m1 = nm1;
        float rs0 = 0.f, rs1 = 0.f;
        #pragma unroll
        for (int nt = 0; nt < 8; nt++) {
            s[nt][0] = __expf(s[nt][0] - m0);
            s[nt][1] = __expf(s[nt][1] - m0);
            s[nt][2] = __expf(s[nt][2] - m1);
            s[nt][3] = __expf(s[nt][3] - m1);
            rs0 += s[nt][0] + s[nt][1];
            rs1 += s[nt][2] + s[nt][3];
        }
        rs0 += __shfl_xor_sync(0xffffffffu, rs0, 1);
        rs0 += __shfl_xor_sync(0xffffffffu, rs0, 2);
        rs1 += __shfl_xor_sync(0xffffffffu, rs1, 1);
        rs1 += __shfl_xor_sync(0xffffffffu, rs1, 2);
        l0 = l0 * al0 + rs0;
        l1 = l1 * al1 + rs1;
        #pragma unroll
        for (int nt = 0; nt < 8; nt++) {
            o[nt][0] *= al0; o[nt][1] *= al0;
            o[nt][2] *= al1; o[nt][3] *= al1;
        }

        // ---- O += P @ V : P reshaped via shuffles, V-fragments via LDS.128 ----
        #pragma unroll
        for (int ks = 0; ks < 8; ks++) {
            unsigned u0 = f2tf(s[ks][0]), u1 = f2tf(s[ks][1]);
            unsigned u2 = f2tf(s[ks][2]), u3 = f2tf(s[ks][3]);
            unsigned xa0 = __shfl_sync(0xffffffffu, u0, srcA);
            unsigned xa1 = __shfl_sync(0xffffffffu, u1, srcA);
            unsigned ya0 = __shfl_sync(0xffffffffu, u2, srcA);
            unsigned ya1 = __shfl_sync(0xffffffffu, u3, srcA);
            unsigned xb0 = __shfl_sync(0xffffffffu, u0, srcB);
            unsigned xb1 = __shfl_sync(0xffffffffu, u1, srcB);
            unsigned yb0 = __shfl_sync(0xffffffffu, u2, srcB);
            unsigned yb1 = __shfl_sync(0xffffffffu, u3, srcB);
            unsigned a0 = eo ? xa1 : xa0;
            unsigned a1 = eo ? ya1 : ya0;
            unsigned a2 = eo ? xb1 : xb0;
            unsigned a3 = eo ? yb1 : yb0;
            uint4 v0a = *(const uint4*)&Vp[(ks * 8 + tr) * KP + tq * 8];
            uint4 v0b = *(const uint4*)&Vp[(ks * 8 + tr) * KP + tq * 8 + 4];
            uint4 v1a = *(const uint4*)&Vp[(ks * 8 + tr + 4) * KP + tq * 8];
            uint4 v1b = *(const uint4*)&Vp[(ks * 8 + tr + 4) * KP + tq * 8 + 4];
            mma_tf32(o[0], a0, a1, a2, a3, v0a.x, v1a.x);
            mma_tf32(o[1], a0, a1, a2, a3, v0a.y, v1a.y);
            mma_tf32(o[2], a0, a1, a2, a3, v0a.z, v1a.z);
            mma_tf32(o[3], a0, a1, a2, a3, v0a.w, v1a.w);
            mma_tf32(o[4], a0, a1, a2, a3, v0b.x, v1b.x);
            mma_tf32(o[5], a0, a1, a2, a3, v0b.y, v1b.y);
            mma_tf32(o[6], a0, a1, a2, a3, v0b.z, v1b.z);
            mma_tf32(o[7], a0, a1, a2, a3, v0b.w, v1b.w);
        }
    }

    float inv0 = 1.f / l0, inv1 = 1.f / l1;
    float* ob = g_ao + (size_t)(b * T_ + qrow) * C_ + h * HD;
    #pragma unroll
    for (int nt = 0; nt < 8; nt++) {
        *(float2*)&ob[(size_t)tq * C_ + nt * 8 + 2 * tr] =
            make_float2(o[nt][0] * inv0, o[nt][1] * inv0);
        *(float2*)&ob[(size_t)(tq + 8) * C_ + nt * 8 + 2 * tr] =
            make_float2(o[nt][2] * inv1, o[nt][3] * inv1);
    }
}

// ---------------- launch ----------------
extern "C" void kernel_launch(void* const* d_in, const int* in_sizes, int n_in,
                              void* d_out, int out_size) {
    const float* x    = (const float*)d_in[0];
    const float* kc   = (const float*)d_in[1];
    const float* vc   = (const float*)d_in[2];
    const int*   pidx = (const int*)  d_in[3];
    const float* Wq   = (const float*)d_in[4];
    const float* Wk   = (const float*)d_in[5];
    const float* Wv   = (const float*)d_in[6];
    const float* Wo   = (const float*)d_in[7];

    float* out  = (float*)d_out;
    float* kout = out + 2 * 1024 * 1024;
    float* vout = kout + 2 * 4 * 2048 * 64;

    float *gq, *gao;
    cudaGetSymbolAddress((void**)&gq,  g_q);
    cudaGetSymbolAddress((void**)&gao, g_ao);

    cudaFuncSetAttribute(qkv_gemm, cudaFuncAttributeMaxDynamicSharedMemorySize, GSM);
    cudaFuncSetAttribute(o_gemm,   cudaFuncAttributeMaxDynamicSharedMemorySize, GSM);
    cudaFuncSetAttribute(attn_k,   cudaFuncAttributeMaxDynamicSharedMemorySize, ASM);

    invf_init<<<1, 32>>>();
    rope_tab<<<(ROWS * 32) / 256, 256>>>(pidx);

    dim3 gqkv(24, 16);
    qkv_gemm<<<gqkv, 128, GSM>>>(x, Wq, Wk, Wv, kout, vout);

    int nc = B_ * NKV * 1024 * 16;
    copy_cache<<<(nc + 255) / 256, 256>>>(kc, vc, kout, vout);

    dim3 ga(T_ / 128, NH, B_);
    attn_k<<<ga, 256, ASM>>>(kout, vout);

    dim3 go(16, 16);
    o_gemm<<<go, 128, GSM>>>(gao, Wo, out);
}

// round 6
// speedup vs baseline: 1.2369x; 1.2369x over previous
#include <cuda_runtime.h>
#include <math.h>

#define B_   2
#define T_   1024
#define C_   1024
#define NH   16
#define NKV  4
#define HD   64
#define S_   2048
#define ROWS 2048
#define KVW  (NKV*HD)

// ---------------- scratch ----------------
__device__ float g_q [ROWS * C_];
__device__ float g_ao[ROWS * C_];
__device__ float g_cos[ROWS * 32];
__device__ float g_sin[ROWS * 32];

// ---------------- helpers ----------------
__device__ __forceinline__ unsigned f2tf(float x) {
    unsigned u;
    asm("cvt.rna.tf32.f32 %0, %1;" : "=r"(u) : "f"(x));
    return u;
}
__device__ __forceinline__ void mma_tf32(float* c,
                                         unsigned a0, unsigned a1, unsigned a2, unsigned a3,
                                         unsigned b0, unsigned b1) {
    asm volatile(
        "mma.sync.aligned.m16n8k8.row.col.f32.tf32.tf32.f32 "
        "{%0,%1,%2,%3}, {%4,%5,%6,%7}, {%8,%9}, {%0,%1,%2,%3};"
        : "+f"(c[0]), "+f"(c[1]), "+f"(c[2]), "+f"(c[3])
        : "r"(a0), "r"(a1), "r"(a2), "r"(a3), "r"(b0), "r"(b1));
}
__device__ __forceinline__ void cpa16(unsigned s, const float* g) {
    asm volatile("cp.async.ca.shared.global [%0], [%1], 16;" :: "r"(s), "l"(g));
}
__device__ __forceinline__ void cpa_commit() { asm volatile("cp.async.commit_group;"); }

// ---------------- GEMM core: 128M x 64N tile, 128 threads, K=1024, cp.async x2 ----------------
#define AS 36
#define BS 72
#define GSM ((2*128*AS + 2*32*BS) * 4)   // 55296 B

__device__ __forceinline__ void gemm_main(const float* __restrict__ A,
                                          const float* __restrict__ Bw,
                                          int ldB, int m0, int n0,
                                          float acc[2][8][4], float* smf) {
    float* A_s = smf;
    float* B_s = smf + 2 * 128 * AS;
    const int tid = threadIdx.x;
    unsigned aBase = (unsigned)__cvta_generic_to_shared(A_s);
    unsigned bBase = (unsigned)__cvta_generic_to_shared(B_s);

    const int arow = tid >> 3, ac4 = (tid & 7) << 2;
    const int brow = tid >> 4, bc4 = (tid & 15) << 2;

    #pragma unroll
    for (int i = 0; i < 8; i++)
        cpa16(aBase + (((arow + i * 16) * AS + ac4) << 2),
              &A[(size_t)(m0 + arow + i * 16) * 1024 + ac4]);
    #pragma unroll
    for (int i = 0; i < 4; i++)
        cpa16(bBase + (((brow + i * 8) * BS + bc4) << 2),
              &Bw[(size_t)(brow + i * 8) * ldB + n0 + bc4]);
    cpa_commit();

    const int lane = tid & 31, warp = tid >> 5;
    const int tq = lane >> 2, tr = lane & 3;
    int buf = 0;
    for (int c = 0; c < 32; c++) {
        if (c < 31) {
            int kc = (c + 1) * 32;
            int nb = buf ^ 1;
            #pragma unroll
            for (int i = 0; i < 8; i++)
                cpa16(aBase + ((((nb * 128) + arow + i * 16) * AS + ac4) << 2),
                      &A[(size_t)(m0 + arow + i * 16) * 1024 + kc + ac4]);
            #pragma unroll
            for (int i = 0; i < 4; i++)
                cpa16(bBase + ((((nb * 32) + brow + i * 8) * BS + bc4) << 2),
                      &Bw[(size_t)(kc + brow + i * 8) * ldB + n0 + bc4]);
            cpa_commit();
            asm volatile("cp.async.wait_group 1;");
        } else {
            asm volatile("cp.async.wait_group 0;");
        }
        __syncthreads();

        const float* Ab = A_s + buf * 128 * AS;
        const float* Bb = B_s + buf * 32 * BS;
        #pragma unroll
        for (int ks = 0; ks < 4; ks++) {
            unsigned a[2][4];
            #pragma unroll
            for (int mt = 0; mt < 2; mt++) {
                const float* p = &Ab[(warp * 32 + mt * 16 + tq) * AS + ks * 8 + tr];
                a[mt][0] = f2tf(p[0]);
                a[mt][1] = f2tf(p[8 * AS]);
                a[mt][2] = f2tf(p[4]);
                a[mt][3] = f2tf(p[8 * AS + 4]);
            }
            #pragma unroll
            for (int nt = 0; nt < 8; nt++) {
                unsigned b0 = f2tf(Bb[(ks * 8 + tr) * BS + nt * 8 + tq]);
                unsigned b1 = f2tf(Bb[(ks * 8 + tr + 4) * BS + nt * 8 + tq]);
                mma_tf32(acc[0][nt], a[0][0], a[0][1], a[0][2], a[0][3], b0, b1);
                mma_tf32(acc[1][nt], a[1][0], a[1][1], a[1][2], a[1][3], b0, b1);
            }
        }
        __syncthreads();
        buf ^= 1;
    }
}

// rope rotate in registers: pairs (nt, nt+4)
__device__ __forceinline__ void rope_acc(float acc[2][8][4], int m0) {
    const int lane = threadIdx.x & 31, warp = threadIdx.x >> 5;
    const int tq = lane >> 2, tr = lane & 3;
    #pragma unroll
    for (int mt = 0; mt < 2; mt++) {
        int r0 = m0 + warp * 32 + mt * 16 + tq;
        int r1 = r0 + 8;
        #pragma unroll
        for (int nt = 0; nt < 4; nt++) {
            int i0 = nt * 8 + 2 * tr;
            float2 c0 = *(const float2*)&g_cos[r0 * 32 + i0];
            float2 s0 = *(const float2*)&g_sin[r0 * 32 + i0];
            float2 c1 = *(const float2*)&g_cos[r1 * 32 + i0];
            float2 s1 = *(const float2*)&g_sin[r1 * 32 + i0];
            float x1, x2;
            x1 = acc[mt][nt][0]; x2 = acc[mt][nt + 4][0];
            acc[mt][nt][0] = x1 * c0.x - x2 * s0.x;  acc[mt][nt + 4][0] = x2 * c0.x + x1 * s0.x;
            x1 = acc[mt][nt][1]; x2 = acc[mt][nt + 4][1];
            acc[mt][nt][1] = x1 * c0.y - x2 * s0.y;  acc[mt][nt + 4][1] = x2 * c0.y + x1 * s0.y;
            x1 = acc[mt][nt][2]; x2 = acc[mt][nt + 4][2];
            acc[mt][nt][2] = x1 * c1.x - x2 * s1.x;  acc[mt][nt + 4][2] = x2 * c1.x + x1 * s1.x;
            x1 = acc[mt][nt][3]; x2 = acc[mt][nt + 4][3];
            acc[mt][nt][3] = x1 * c1.y - x2 * s1.y;  acc[mt][nt + 4][3] = x2 * c1.y + x1 * s1.y;
        }
    }
}

// ---------------- merged QKV projection (+rope, +scatter) ----------------
__global__ __launch_bounds__(128, 4) void qkv_gemm(const float* __restrict__ x,
                                                   const float* __restrict__ Wq,
                                                   const float* __restrict__ Wk,
                                                   const float* __restrict__ Wv,
                                                   float* __restrict__ kout,
                                                   float* __restrict__ vout) {
    extern __shared__ float smf[];
    const int bx = blockIdx.x, m0 = blockIdx.y * 128;
    const float* Bw; int ldB, n0, mode;
    if (bx < 16)      { Bw = Wq; ldB = 1024; n0 = bx * 64;        mode = 0; }
    else if (bx < 20) { Bw = Wk; ldB = 256;  n0 = (bx - 16) * 64; mode = 1; }
    else              { Bw = Wv; ldB = 256;  n0 = (bx - 20) * 64; mode = 2; }

    float acc[2][8][4];
    #pragma unroll
    for (int i = 0; i < 2; i++)
        #pragma unroll
        for (int j = 0; j < 8; j++)
            #pragma unroll
            for (int k = 0; k < 4; k++) acc[i][j][k] = 0.f;

    gemm_main(x, Bw, ldB, m0, n0, acc, smf);

    if (mode != 2) rope_acc(acc, m0);

    const int lane = threadIdx.x & 31, warp = threadIdx.x >> 5;
    const int tq = lane >> 2, tr = lane & 3;
    #pragma unroll
    for (int mt = 0; mt < 2; mt++) {
        int r = m0 + warp * 32 + mt * 16 + tq;
        if (mode == 0) {
            float* p0 = &g_q[(size_t)r * C_ + n0];
            float* p1 = &g_q[(size_t)(r + 8) * C_ + n0];
            #pragma unroll
            for (int nt = 0; nt < 8; nt++) {
                *(float2*)&p0[nt * 8 + 2 * tr] = make_float2(acc[mt][nt][0], acc[mt][nt][1]);
                *(float2*)&p1[nt * 8 + 2 * tr] = make_float2(acc[mt][nt][2], acc[mt][nt][3]);
            }
        } else {
            int b = r >> 10, t = r & 1023;
            int kv = (mode == 1) ? (bx - 16) : (bx - 20);
            float* dst = (mode == 1) ? kout : vout;
            float* p0 = &dst[(size_t)((b * NKV + kv) * S_ + 1024 + t) * HD];
            float* p1 = &dst[(size_t)((b * NKV + kv) * S_ + 1024 + t + 8) * HD];
            #pragma unroll
            for (int nt = 0; nt < 8; nt++) {
                *(float2*)&p0[nt * 8 + 2 * tr] = make_float2(acc[mt][nt][0], acc[mt][nt][1]);
                *(float2*)&p1[nt * 8 + 2 * tr] = make_float2(acc[mt][nt][2], acc[mt][nt][3]);
            }
        }
    }
}

// ---------------- O projection ----------------
__global__ __launch_bounds__(128, 4) void o_gemm(const float* __restrict__ A,
                                                 const float* __restrict__ Wo,
                                                 float* __restrict__ out) {
    extern __shared__ float smf[];
    const int m0 = blockIdx.y * 128, n0 = blockIdx.x * 64;
    float acc[2][8][4];
    #pragma unroll
    for (int i = 0; i < 2; i++)
        #pragma unroll
        for (int j = 0; j < 8; j++)
            #pragma unroll
            for (int k = 0; k < 4; k++) acc[i][j][k] = 0.f;

    gemm_main(A, Wo, 1024, m0, n0, acc, smf);

    const int lane = threadIdx.x & 31, warp = threadIdx.x >> 5;
    const int tq = lane >> 2, tr = lane & 3;
    #pragma unroll
    for (int mt = 0; mt < 2; mt++) {
        int r = m0 + warp * 32 + mt * 16 + tq;
        float* p0 = &out[(size_t)r * C_ + n0];
        float* p1 = &out[(size_t)(r + 8) * C_ + n0];
        #pragma unroll
        for (int nt = 0; nt < 8; nt++) {
            *(float2*)&p0[nt * 8 + 2 * tr] = make_float2(acc[mt][nt][0], acc[mt][nt][1]);
            *(float2*)&p1[nt * 8 + 2 * tr] = make_float2(acc[mt][nt][2], acc[mt][nt][3]);
        }
    }
}

// ---------------- rope tables (invf computed per-block in double, once) ----------------
__global__ void rope_tab(const int* __restrict__ pidx) {
    __shared__ float invf[32];
    if (threadIdx.x < 32)
        invf[threadIdx.x] = (float)pow(10000.0, -(double)threadIdx.x / 32.0);
    __syncthreads();
    int idx = blockIdx.x * blockDim.x + threadIdx.x;
    if (idx >= ROWS * 32) return;
    int i = idx & 31, row = idx >> 5;
    int p = min(max(pidx[row] + (row & 1023) + 1024, 0), 4095);
    float ang = (float)p * invf[i];
    float c, s;
    sincosf(ang, &s, &c);
    g_cos[idx] = c;
    g_sin[idx] = s;
}

// ---------------- cache halves copy ----------------
__global__ void copy_cache(const float* __restrict__ kc, const float* __restrict__ vc,
                           float* __restrict__ kout, float* __restrict__ vout) {
    int idx = blockIdx.x * blockDim.x + threadIdx.x;
    if (idx >= B_ * NKV * 1024 * 16) return;
    int d4 = idx & 15;
    int s  = (idx >> 4) & 1023;
    int bk = idx >> 14;
    int dst = ((bk * S_) + s) * 16 + d4;
    ((float4*)kout)[dst] = ((const float4*)kc)[idx];
    ((float4*)vout)[dst] = ((const float4*)vc)[idx];
}

// ---------------- Flash attention v6: 64q tiles, 128 threads, occ 4 ----------------
#define KP 68
#define VP 72
#define ASM ((64*KP + 64*VP) * 4)   // 35840 B

__global__ __launch_bounds__(128, 4) void attn_k(const float* __restrict__ kall,
                                                 const float* __restrict__ vall) {
    extern __shared__ unsigned sm[];
    unsigned* K_s = sm;             // [64 keys][KP] (d-major per key row)
    unsigned* V_s = sm + 64 * KP;   // [64 keys][VP]

    const int tid = threadIdx.x, lane = tid & 31, warp = tid >> 5;
    const int tq = lane >> 2, tr = lane & 3;
    const int qt = blockIdx.x, h = blockIdx.y, b = blockIdx.z;
    const float* kb = kall + (size_t)(b * NKV + (h >> 2)) * S_ * HD;
    const float* vb = vall + (size_t)(b * NKV + (h >> 2)) * S_ * HD;
    const int qrow = qt * 64 + warp * 16;

    // Q fragments (scale folded), registers for the whole kernel
    unsigned qa[8][4];
    const float* qp = g_q + (size_t)(b * T_ + qrow) * C_ + h * HD;
    #pragma unroll
    for (int ks = 0; ks < 8; ks++) {
        qa[ks][0] = f2tf(qp[(size_t)tq * C_ + ks * 8 + tr] * 0.125f);
        qa[ks][1] = f2tf(qp[(size_t)(tq + 8) * C_ + ks * 8 + tr] * 0.125f);
        qa[ks][2] = f2tf(qp[(size_t)tq * C_ + ks * 8 + tr + 4] * 0.125f);
        qa[ks][3] = f2tf(qp[(size_t)(tq + 8) * C_ + ks * 8 + tr + 4] * 0.125f);
    }

    float m0 = -1e30f, m1 = -1e30f, l0 = 0.f, l1 = 0.f;
    float o[8][4];
    #pragma unroll
    for (int nt = 0; nt < 8; nt++)
        #pragma unroll
        for (int k = 0; k < 4; k++) o[nt][k] = 0.f;

    const int srcA = (lane & 28) | ((lane >> 1) & 1);
    const int srcB = srcA + 2;
    const bool eo = lane & 1;

    for (int c0 = 0; c0 < S_; c0 += 64) {
        __syncthreads();
        // fill: 64 rows x 16 float4 each for K and V, 128 threads
        #pragma unroll
        for (int i = 0; i < 8; i++) {
            int idx = tid + i * 128;
            int row = idx >> 4, d4 = (idx & 15) << 2;
            float4 kq = *(const float4*)&kb[(size_t)(c0 + row) * HD + d4];
            float4 vq = *(const float4*)&vb[(size_t)(c0 + row) * HD + d4];
            uint4 ku = make_uint4(f2tf(kq.x), f2tf(kq.y), f2tf(kq.z), f2tf(kq.w));
            uint4 vu = make_uint4(f2tf(vq.x), f2tf(vq.y), f2tf(vq.z), f2tf(vq.w));
            *(uint4*)&K_s[row * KP + d4] = ku;
            *(uint4*)&V_s[row * VP + d4] = vu;
        }
        __syncthreads();

        // S = Q @ K^T
        float s[8][4];
        #pragma unroll
        for (int nt = 0; nt < 8; nt++)
            #pragma unroll
            for (int k = 0; k < 4; k++) s[nt][k] = 0.f;
        #pragma unroll
        for (int ks = 0; ks < 8; ks++)
            #pragma unroll
            for (int nt = 0; nt < 8; nt++) {
                unsigned b0 = K_s[(nt * 8 + tq) * KP + ks * 8 + tr];
                unsigned b1 = K_s[(nt * 8 + tq) * KP + ks * 8 + tr + 4];
                mma_tf32(s[nt], qa[ks][0], qa[ks][1], qa[ks][2], qa[ks][3], b0, b1);
            }

        // online softmax
        float mx0 = -1e30f, mx1 = -1e30f;
        #pragma unroll
        for (int nt = 0; nt < 8; nt++) {
            mx0 = fmaxf(mx0, fmaxf(s[nt][0], s[nt][1]));
            mx1 = fmaxf(mx1, fmaxf(s[nt][2], s[nt][3]));
        }
        mx0 = fmaxf(mx0, __shfl_xor_sync(0xffffffffu, mx0, 1));
        mx0 = fmaxf(mx0, __shfl_xor_sync(0xffffffffu, mx0, 2));
        mx1 = fmaxf(mx1, __shfl_xor_sync(0xffffffffu, mx1, 1));
        mx1 = fmaxf(mx1, __shfl_xor_sync(0xffffffffu, mx1, 2));
        float nm0 = fmaxf(m0, mx0), nm1 = fmaxf(m1, mx1);
        float al0 = __expf(m0 - nm0), al1 = __expf(m1 - nm1);
        m0 = nm0; m1 = nm1;
        float rs0 = 0.f, rs1 = 0.f;
        #pragma unroll
        for (int nt = 0; nt < 8; nt++) {
            s[nt][0] = __expf(s[nt][0] - m0);
            s[nt][1] = __expf(s[nt][1] - m0);
            s[nt][2] = __expf(s[nt][2] - m1);
            s[nt][3] = __expf(s[nt][3] - m1);
            rs0 += s[nt][0] + s[nt][1];
            rs1 += s[nt][2] + s[nt][3];
        }
        rs0 += __shfl_xor_sync(0xffffffffu, rs0, 1);
        rs0 += __shfl_xor_sync(0xffffffffu, rs0, 2);
        rs1 += __shfl_xor_sync(0xffffffffu, rs1, 1);
        rs1 += __shfl_xor_sync(0xffffffffu, rs1, 2);
        l0 = l0 * al0 + rs0;
        l1 = l1 * al1 + rs1;
        #pragma unroll
        for (int nt = 0; nt < 8; nt++) {
            o[nt][0] *= al0; o[nt][1] *= al0;
            o[nt][2] *= al1; o[nt][3] *= al1;
        }

        // O += P @ V (P reshaped C-frag -> A-frag via shuffles)
        #pragma unroll
        for (int ks = 0; ks < 8; ks++) {
            unsigned u0 = f2tf(s[ks][0]), u1 = f2tf(s[ks][1]);
            unsigned u2 = f2tf(s[ks][2]), u3 = f2tf(s[ks][3]);
            unsigned xa0 = __shfl_sync(0xffffffffu, u0, srcA);
            unsigned xa1 = __shfl_sync(0xffffffffu, u1, srcA);
            unsigned ya0 = __shfl_sync(0xffffffffu, u2, srcA);
            unsigned ya1 = __shfl_sync(0xffffffffu, u3, srcA);
            unsigned xb0 = __shfl_sync(0xffffffffu, u0, srcB);
            unsigned xb1 = __shfl_sync(0xffffffffu, u1, srcB);
            unsigned yb0 = __shfl_sync(0xffffffffu, u2, srcB);
            unsigned yb1 = __shfl_sync(0xffffffffu, u3, srcB);
            unsigned a0 = eo ? xa1 : xa0;
            unsigned a1 = eo ? ya1 : ya0;
            unsigned a2 = eo ? xb1 : xb0;
            unsigned a3 = eo ? yb1 : yb0;
            #pragma unroll
            for (int dt = 0; dt < 8; dt++) {
                unsigned b0 = V_s[(ks * 8 + tr) * VP + dt * 8 + tq];
                unsigned b1 = V_s[(ks * 8 + tr + 4) * VP + dt * 8 + tq];
                mma_tf32(o[dt], a0, a1, a2, a3, b0, b1);
            }
        }
    }

    float inv0 = 1.f / l0, inv1 = 1.f / l1;
    float* ob = g_ao + (size_t)(b * T_ + qrow) * C_ + h * HD;
    #pragma unroll
    for (int nt = 0; nt < 8; nt++) {
        *(float2*)&ob[(size_t)tq * C_ + nt * 8 + 2 * tr] =
            make_float2(o[nt][0] * inv0, o[nt][1] * inv0);
        *(float2*)&ob[(size_t)(tq + 8) * C_ + nt * 8 + 2 * tr] =
            make_float2(o[nt][2] * inv1, o[nt][3] * inv1);
    }
}

// ---------------- launch ----------------
extern "C" void kernel_launch(void* const* d_in, const int* in_sizes, int n_in,
                              void* d_out, int out_size) {
    const float* x    = (const float*)d_in[0];
    const float* kc   = (const float*)d_in[1];
    const float* vc   = (const float*)d_in[2];
    const int*   pidx = (const int*)  d_in[3];
    const float* Wq   = (const float*)d_in[4];
    const float* Wk   = (const float*)d_in[5];
    const float* Wv   = (const float*)d_in[6];
    const float* Wo   = (const float*)d_in[7];

    float* out  = (float*)d_out;
    float* kout = out + 2 * 1024 * 1024;
    float* vout = kout + 2 * 4 * 2048 * 64;

    float *gq, *gao;
    cudaGetSymbolAddress((void**)&gq,  g_q);
    cudaGetSymbolAddress((void**)&gao, g_ao);

    cudaFuncSetAttribute(qkv_gemm, cudaFuncAttributeMaxDynamicSharedMemorySize, GSM);
    cudaFuncSetAttribute(o_gemm,   cudaFuncAttributeMaxDynamicSharedMemorySize, GSM);
    cudaFuncSetAttribute(attn_k,   cudaFuncAttributeMaxDynamicSharedMemorySize, ASM);

    rope_tab<<<(ROWS * 32) / 256, 256>>>(pidx);               // launch 0

    dim3 gqkv(24, 16);
    qkv_gemm<<<gqkv, 128, GSM>>>(x, Wq, Wk, Wv, kout, vout);  // launch 1

    int nc = B_ * NKV * 1024 * 16;
    copy_cache<<<(nc + 255) / 256, 256>>>(kc, vc, kout, vout);// launch 2

    dim3 ga(T_ / 64, NH, B_);                                 // (16,16,2) = 512 CTAs
    attn_k<<<ga, 128, ASM>>>(kout, vout);                     // launch 3  (profiled)

    dim3 go(16, 16);
    o_gemm<<<go, 128, GSM>>>(gao, Wo, out);                   // launch 4
}

// round 8
// speedup vs baseline: 1.8473x; 1.4936x over previous
#include <cuda_runtime.h>
#include <cuda_fp16.h>
#include <math.h>
#include <stdint.h>

#define B_   2
#define T_   1024
#define C_   1024
#define NH   16
#define NKV  4
#define HD   64
#define S_   2048
#define ROWS 2048

// ---------------- scratch ----------------
__device__ float  g_ao[ROWS * C_];
__device__ float  g_cos[ROWS * 32];
__device__ float  g_sin[ROWS * 32];
__device__ __half g_qh [ROWS * C_];        // q * 0.125, roped, half
__device__ __half g_kh [8 * S_ * HD];      // K half, [bk][s][d]
__device__ __half g_vTh[8 * HD * S_];      // V^T half, [bk][d][s]

// ---------------- helpers ----------------
__device__ __forceinline__ unsigned f2tf(float x) {
    unsigned u;
    asm("cvt.rna.tf32.f32 %0, %1;" : "=r"(u) : "f"(x));
    return u;
}
__device__ __forceinline__ unsigned pack2(float lo, float hi) {
    unsigned u;
    asm("cvt.rn.f16x2.f32 %0, %1, %2;" : "=r"(u) : "f"(hi), "f"(lo));
    return u;
}
__device__ __forceinline__ void mma_tf32(float* c,
                                         unsigned a0, unsigned a1, unsigned a2, unsigned a3,
                                         unsigned b0, unsigned b1) {
    asm volatile(
        "mma.sync.aligned.m16n8k8.row.col.f32.tf32.tf32.f32 "
        "{%0,%1,%2,%3}, {%4,%5,%6,%7}, {%8,%9}, {%0,%1,%2,%3};"
        : "+f"(c[0]), "+f"(c[1]), "+f"(c[2]), "+f"(c[3])
        : "r"(a0), "r"(a1), "r"(a2), "r"(a3), "r"(b0), "r"(b1));
}
__device__ __forceinline__ void mma_f16(float* c,
                                        unsigned a0, unsigned a1, unsigned a2, unsigned a3,
                                        unsigned b0, unsigned b1) {
    asm volatile(
        "mma.sync.aligned.m16n8k16.row.col.f32.f16.f16.f32 "
        "{%0,%1,%2,%3}, {%4,%5,%6,%7}, {%8,%9}, {%0,%1,%2,%3};"
        : "+f"(c[0]), "+f"(c[1]), "+f"(c[2]), "+f"(c[3])
        : "r"(a0), "r"(a1), "r"(a2), "r"(a3), "r"(b0), "r"(b1));
}
__device__ __forceinline__ void cpa16(unsigned s, const void* g) {
    asm volatile("cp.async.ca.shared.global [%0], [%1], 16;" :: "r"(s), "l"(g));
}
__device__ __forceinline__ void cpa_commit() { asm volatile("cp.async.commit_group;"); }

// ---------------- GEMM core (tf32, unchanged from R3) ----------------
#define AS 36
#define BS 72
#define GSM ((2*128*AS + 2*32*BS) * 4)

__device__ __forceinline__ void gemm_main(const float* __restrict__ A,
                                          const float* __restrict__ Bw,
                                          int ldB, int m0, int n0,
                                          float acc[2][8][4], float* smf) {
    float* A_s = smf;
    float* B_s = smf + 2 * 128 * AS;
    const int tid = threadIdx.x;
    unsigned aBase = (unsigned)__cvta_generic_to_shared(A_s);
    unsigned bBase = (unsigned)__cvta_generic_to_shared(B_s);
    const int arow = tid >> 3, ac4 = (tid & 7) << 2;
    const int brow = tid >> 4, bc4 = (tid & 15) << 2;

    #pragma unroll
    for (int i = 0; i < 8; i++)
        cpa16(aBase + (((arow + i * 16) * AS + ac4) << 2),
              &A[(size_t)(m0 + arow + i * 16) * 1024 + ac4]);
    #pragma unroll
    for (int i = 0; i < 4; i++)
        cpa16(bBase + (((brow + i * 8) * BS + bc4) << 2),
              &Bw[(size_t)(brow + i * 8) * ldB + n0 + bc4]);
    cpa_commit();

    const int lane = tid & 31, warp = tid >> 5;
    const int tq = lane >> 2, tr = lane & 3;
    int buf = 0;
    for (int c = 0; c < 32; c++) {
        if (c < 31) {
            int kc = (c + 1) * 32;
            int nb = buf ^ 1;
            #pragma unroll
            for (int i = 0; i < 8; i++)
                cpa16(aBase + ((((nb * 128) + arow + i * 16) * AS + ac4) << 2),
                      &A[(size_t)(m0 + arow + i * 16) * 1024 + kc + ac4]);
            #pragma unroll
            for (int i = 0; i < 4; i++)
                cpa16(bBase + ((((nb * 32) + brow + i * 8) * BS + bc4) << 2),
                      &Bw[(size_t)(kc + brow + i * 8) * ldB + n0 + bc4]);
            cpa_commit();
            asm volatile("cp.async.wait_group 1;");
        } else {
            asm volatile("cp.async.wait_group 0;");
        }
        __syncthreads();

        const float* Ab = A_s + buf * 128 * AS;
        const float* Bb = B_s + buf * 32 * BS;
        #pragma unroll
        for (int ks = 0; ks < 4; ks++) {
            unsigned a[2][4];
            #pragma unroll
            for (int mt = 0; mt < 2; mt++) {
                const float* p = &Ab[(warp * 32 + mt * 16 + tq) * AS + ks * 8 + tr];
                a[mt][0] = f2tf(p[0]);
                a[mt][1] = f2tf(p[8 * AS]);
                a[mt][2] = f2tf(p[4]);
                a[mt][3] = f2tf(p[8 * AS + 4]);
            }
            #pragma unroll
            for (int nt = 0; nt < 8; nt++) {
                unsigned b0 = f2tf(Bb[(ks * 8 + tr) * BS + nt * 8 + tq]);
                unsigned b1 = f2tf(Bb[(ks * 8 + tr + 4) * BS + nt * 8 + tq]);
                mma_tf32(acc[0][nt], a[0][0], a[0][1], a[0][2], a[0][3], b0, b1);
                mma_tf32(acc[1][nt], a[1][0], a[1][1], a[1][2], a[1][3], b0, b1);
            }
        }
        __syncthreads();
        buf ^= 1;
    }
}

__device__ __forceinline__ void rope_acc(float acc[2][8][4], int m0) {
    const int lane = threadIdx.x & 31, warp = threadIdx.x >> 5;
    const int tq = lane >> 2, tr = lane & 3;
    #pragma unroll
    for (int mt = 0; mt < 2; mt++) {
        int r0 = m0 + warp * 32 + mt * 16 + tq;
        int r1 = r0 + 8;
        #pragma unroll
        for (int nt = 0; nt < 4; nt++) {
            int i0 = nt * 8 + 2 * tr;
            float2 c0 = *(const float2*)&g_cos[r0 * 32 + i0];
            float2 s0 = *(const float2*)&g_sin[r0 * 32 + i0];
            float2 c1 = *(const float2*)&g_cos[r1 * 32 + i0];
            float2 s1 = *(const float2*)&g_sin[r1 * 32 + i0];
            float x1, x2;
            x1 = acc[mt][nt][0]; x2 = acc[mt][nt + 4][0];
            acc[mt][nt][0] = x1 * c0.x - x2 * s0.x;  acc[mt][nt + 4][0] = x2 * c0.x + x1 * s0.x;
            x1 = acc[mt][nt][1]; x2 = acc[mt][nt + 4][1];
            acc[mt][nt][1] = x1 * c0.y - x2 * s0.y;  acc[mt][nt + 4][1] = x2 * c0.y + x1 * s0.y;
            x1 = acc[mt][nt][2]; x2 = acc[mt][nt + 4][2];
            acc[mt][nt][2] = x1 * c1.x - x2 * s1.x;  acc[mt][nt + 4][2] = x2 * c1.x + x1 * s1.x;
            x1 = acc[mt][nt][3]; x2 = acc[mt][nt + 4][3];
            acc[mt][nt][3] = x1 * c1.y - x2 * s1.y;  acc[mt][nt + 4][3] = x2 * c1.y + x1 * s1.y;
        }
    }
}

// ---------------- merged QKV projection (+rope, +scatter, +half side copies) ----------------
__global__ __launch_bounds__(128, 4) void qkv_gemm(const float* __restrict__ x,
                                                   const float* __restrict__ Wq,
                                                   const float* __restrict__ Wk,
                                                   const float* __restrict__ Wv,
                                                   float* __restrict__ kout,
                                                   float* __restrict__ vout) {
    extern __shared__ float smf[];
    const int bx = blockIdx.x, m0 = blockIdx.y * 128;
    const float* Bw; int ldB, n0, mode;
    if (bx < 16)      { Bw = Wq; ldB = 1024; n0 = bx * 64;        mode = 0; }
    else if (bx < 20) { Bw = Wk; ldB = 256;  n0 = (bx - 16) * 64; mode = 1; }
    else              { Bw = Wv; ldB = 256;  n0 = (bx - 20) * 64; mode = 2; }

    float acc[2][8][4];
    #pragma unroll
    for (int i = 0; i < 2; i++)
        #pragma unroll
        for (int j = 0; j < 8; j++)
            #pragma unroll
            for (int k = 0; k < 4; k++) acc[i][j][k] = 0.f;

    gemm_main(x, Bw, ldB, m0, n0, acc, smf);
    if (mode != 2) rope_acc(acc, m0);

    const int lane = threadIdx.x & 31, warp = threadIdx.x >> 5;
    const int tq = lane >> 2, tr = lane & 3;
    #pragma unroll
    for (int mt = 0; mt < 2; mt++) {
        int r = m0 + warp * 32 + mt * 16 + tq;
        if (mode == 0) {
            __half* p0 = &g_qh[(size_t)r * C_ + n0];
            __half* p1 = &g_qh[(size_t)(r + 8) * C_ + n0];
            #pragma unroll
            for (int nt = 0; nt < 8; nt++) {
                *(unsigned*)&p0[nt * 8 + 2 * tr] =
                    pack2(acc[mt][nt][0] * 0.125f, acc[mt][nt][1] * 0.125f);
                *(unsigned*)&p1[nt * 8 + 2 * tr] =
                    pack2(acc[mt][nt][2] * 0.125f, acc[mt][nt][3] * 0.125f);
            }
        } else {
            int b = r >> 10, t = r & 1023;
            int kv = (mode == 1) ? (bx - 16) : (bx - 20);
            int bk = b * NKV + kv;
            float* dst = (mode == 1) ? kout : vout;
            float* p0 = &dst[(size_t)(bk * S_ + 1024 + t) * HD];
            float* p1 = &dst[(size_t)(bk * S_ + 1024 + t + 8) * HD];
            #pragma unroll
            for (int nt = 0; nt < 8; nt++) {
                *(float2*)&p0[nt * 8 + 2 * tr] = make_float2(acc[mt][nt][0], acc[mt][nt][1]);
                *(float2*)&p1[nt * 8 + 2 * tr] = make_float2(acc[mt][nt][2], acc[mt][nt][3]);
            }
            if (mode == 1) {
                __half* q0 = &g_kh[(size_t)(bk * S_ + 1024 + t) * HD];
                __half* q1 = &g_kh[(size_t)(bk * S_ + 1024 + t + 8) * HD];
                #pragma unroll
                for (int nt = 0; nt < 8; nt++) {
                    *(unsigned*)&q0[nt * 8 + 2 * tr] = pack2(acc[mt][nt][0], acc[mt][nt][1]);
                    *(unsigned*)&q1[nt * 8 + 2 * tr] = pack2(acc[mt][nt][2], acc[mt][nt][3]);
                }
            } else {
                __half* vt = g_vTh + (size_t)bk * HD * S_;
                #pragma unroll
                for (int nt = 0; nt < 8; nt++) {
                    int d = nt * 8 + 2 * tr;
                    vt[(size_t)d * S_ + 1024 + t]           = __float2half_rn(acc[mt][nt][0]);
                    vt[(size_t)(d + 1) * S_ + 1024 + t]     = __float2half_rn(acc[mt][nt][1]);
                    vt[(size_t)d * S_ + 1024 + t + 8]       = __float2half_rn(acc[mt][nt][2]);
                    vt[(size_t)(d + 1) * S_ + 1024 + t + 8] = __float2half_rn(acc[mt][nt][3]);
                }
            }
        }
    }
}

// ---------------- O projection (tf32) ----------------
__global__ __launch_bounds__(128, 4) void o_gemm(const float* __restrict__ A,
                                                 const float* __restrict__ Wo,
                                                 float* __restrict__ out) {
    extern __shared__ float smf[];
    const int m0 = blockIdx.y * 128, n0 = blockIdx.x * 64;
    float acc[2][8][4];
    #pragma unroll
    for (int i = 0; i < 2; i++)
        #pragma unroll
        for (int j = 0; j < 8; j++)
            #pragma unroll
            for (int k = 0; k < 4; k++) acc[i][j][k] = 0.f;

    gemm_main(A, Wo, 1024, m0, n0, acc, smf);

    const int lane = threadIdx.x & 31, warp = threadIdx.x >> 5;
    const int tq = lane >> 2, tr = lane & 3;
    #pragma unroll
    for (int mt = 0; mt < 2; mt++) {
        int r = m0 + warp * 32 + mt * 16 + tq;
        float* p0 = &out[(size_t)r * C_ + n0];
        float* p1 = &out[(size_t)(r + 8) * C_ + n0];
        #pragma unroll
        for (int nt = 0; nt < 8; nt++) {
            *(float2*)&p0[nt * 8 + 2 * tr] = make_float2(acc[mt][nt][0], acc[mt][nt][1]);
            *(float2*)&p1[nt * 8 + 2 * tr] = make_float2(acc[mt][nt][2], acc[mt][nt][3]);
        }
    }
}

// ---------------- rope tables ----------------
__global__ void rope_tab(const int* __restrict__ pidx) {
    __shared__ float invf[32];
    if (threadIdx.x < 32)
        invf[threadIdx.x] = (float)pow(10000.0, -(double)threadIdx.x / 32.0);
    __syncthreads();
    int idx = blockIdx.x * blockDim.x + threadIdx.x;
    if (idx >= ROWS * 32) return;
    int i = idx & 31, row = idx >> 5;
    int p = min(max(pidx[row] + (row & 1023) + 1024, 0), 4095);
    float ang = (float)p * invf[i];
    float c, s;
    sincosf(ang, &s, &c);
    g_cos[idx] = c;
    g_sin[idx] = s;
}

// ---------------- cache halves copy (+half side copies) ----------------
__global__ void copy_cache(const float* __restrict__ kc, const float* __restrict__ vc,
                           float* __restrict__ kout, float* __restrict__ vout) {
    int idx = blockIdx.x * blockDim.x + threadIdx.x;
    if (idx >= B_ * NKV * 1024 * 16) return;
    int d4 = idx & 15;
    int s  = (idx >> 4) & 1023;
    int bk = idx >> 14;
    int dst = ((bk * S_) + s) * 16 + d4;
    float4 kq = ((const float4*)kc)[idx];
    float4 vq = ((const float4*)vc)[idx];
    ((float4*)kout)[dst] = kq;
    ((float4*)vout)[dst] = vq;
    __half* kh = &g_kh[(size_t)dst * 4];
    *(unsigned*)&kh[0] = pack2(kq.x, kq.y);
    *(unsigned*)&kh[2] = pack2(kq.z, kq.w);
    __half* vt = g_vTh + (size_t)bk * HD * S_;
    int d0 = d4 * 4;
    vt[(size_t)d0 * S_ + s]       = __float2half_rn(vq.x);
    vt[(size_t)(d0 + 1) * S_ + s] = __float2half_rn(vq.y);
    vt[(size_t)(d0 + 2) * S_ + s] = __float2half_rn(vq.z);
    vt[(size_t)(d0 + 3) * S_ + s] = __float2half_rn(vq.w);
}

// ---------------- Flash attention v8: fp16 m16n8k16 ----------------
// K_s [64 key][KHP halves] natural; Vt_s [64 d][KHP] (V^T). No P shuffles:
// C-fragment of S maps directly onto A-fragment of PV.
#define KHP 72
#define AHSM (2 * 64 * KHP * 2)   // 18432 B

__global__ __launch_bounds__(256, 2) void attn_h() {
    extern __shared__ __half smh[];
    __half* K_s  = smh;
    __half* Vt_s = smh + 64 * KHP;

    const int tid = threadIdx.x, lane = tid & 31, warp = tid >> 5;
    const int tq = lane >> 2, tr = lane & 3;
    const int qt = blockIdx.x, h = blockIdx.y, b = blockIdx.z;
    const int bk = b * NKV + (h >> 2);
    const __half* kh  = g_kh  + (size_t)bk * S_ * HD;
    const __half* vth = g_vTh + (size_t)bk * HD * S_;
    const __half* qh  = g_qh  + (size_t)(b * T_ + qt * 128 + warp * 16) * C_ + h * HD;

    // Q fragments (half2), resident all kernel
    unsigned qa[4][4];
    #pragma unroll
    for (int kc = 0; kc < 4; kc++) {
        qa[kc][0] = *(const unsigned*)&qh[(size_t)tq * C_ + kc * 16 + 2 * tr];
        qa[kc][1] = *(const unsigned*)&qh[(size_t)(tq + 8) * C_ + kc * 16 + 2 * tr];
        qa[kc][2] = *(const unsigned*)&qh[(size_t)tq * C_ + kc * 16 + 2 * tr + 8];
        qa[kc][3] = *(const unsigned*)&qh[(size_t)(tq + 8) * C_ + kc * 16 + 2 * tr + 8];
    }

    float m0 = -1e30f, m1 = -1e30f, l0 = 0.f, l1 = 0.f;
    float o[8][4];
    #pragma unroll
    for (int nt = 0; nt < 8; nt++)
        #pragma unroll
        for (int k = 0; k < 4; k++) o[nt][k] = 0.f;

    for (int c0 = 0; c0 < S_; c0 += 64) {
        __syncthreads();
        // fill: K tile (natural) + V^T tile, 16B vector copies
        #pragma unroll
        for (int p = 0; p < 2; p++) {
            int idx = tid + p * 256;         // 512 uint4 total
            int row = idx >> 3, j8 = (idx & 7) * 8;
            *(uint4*)&K_s[row * KHP + j8] =
                *(const uint4*)&kh[(size_t)(c0 + row) * HD + j8];
            *(uint4*)&Vt_s[row * KHP + j8] =
                *(const uint4*)&vth[(size_t)row * S_ + c0 + j8];
        }
        __syncthreads();

        // S = Q @ K^T
        float s[8][4];
        #pragma unroll
        for (int nt = 0; nt < 8; nt++)
            #pragma unroll
            for (int k = 0; k < 4; k++) s[nt][k] = 0.f;
        #pragma unroll
        for (int kc = 0; kc < 4; kc++)
            #pragma unroll
            for (int nt = 0; nt < 8; nt++) {
                unsigned b0 = *(const unsigned*)&K_s[(nt * 8 + tq) * KHP + kc * 16 + 2 * tr];
                unsigned b1 = *(const unsigned*)&K_s[(nt * 8 + tq) * KHP + kc * 16 + 2 * tr + 8];
                mma_f16(s[nt], qa[kc][0], qa[kc][1], qa[kc][2], qa[kc][3], b0, b1);
            }

        // online softmax
        float mx0 = -1e30f, mx1 = -1e30f;
        #pragma unroll
        for (int nt = 0; nt < 8; nt++) {
            mx0 = fmaxf(mx0, fmaxf(s[nt][0], s[nt][1]));
            mx1 = fmaxf(mx1, fmaxf(s[nt][2], s[nt][3]));
        }
        mx0 = fmaxf(mx0, __shfl_xor_sync(0xffffffffu, mx0, 1));
        mx0 = fmaxf(mx0, __shfl_xor_sync(0xffffffffu, mx0, 2));
        mx1 = fmaxf(mx1, __shfl_xor_sync(0xffffffffu, mx1, 1));
        mx1 = fmaxf(mx1, __shfl_xor_sync(0xffffffffu, mx1, 2));
        float nm0 = fmaxf(m0, mx0), nm1 = fmaxf(m1, mx1);
        float al0 = __expf(m0 - nm0), al1 = __expf(m1 - nm1);
        m0 = nm0; m1 = nm1;
        float rs0 = 0.f, rs1 = 0.f;
        #pragma unroll
        for (int nt = 0; nt < 8; nt++) {
            s[nt][0] = __expf(s[nt][0] - m0);
            s[nt][1] = __expf(s[nt][1] - m0);
            s[nt][2] = __expf(s[nt][2] - m1);
            s[nt][3] = __expf(s[nt][3] - m1);
            rs0 += s[nt][0] + s[nt][1];
            rs1 += s[nt][2] + s[nt][3];
        }
        rs0 += __shfl_xor_sync(0xffffffffu, rs0, 1);
        rs0 += __shfl_xor_sync(0xffffffffu, rs0, 2);
        rs1 += __shfl_xor_sync(0xffffffffu, rs1, 1);
        rs1 += __shfl_xor_sync(0xffffffffu, rs1, 2);
        l0 = l0 * al0 + rs0;
        l1 = l1 * al1 + rs1;
        #pragma unroll
        for (int nt = 0; nt < 8; nt++) {
            o[nt][0] *= al0; o[nt][1] *= al0;
            o[nt][2] *= al1; o[nt][3] *= al1;
        }

        // O += P @ V : C-frag of S == A-frag of PV (no shuffles)
        #pragma unroll
        for (int kc = 0; kc < 4; kc++) {
            unsigned a0 = pack2(s[2 * kc][0],     s[2 * kc][1]);
            unsigned a1 = pack2(s[2 * kc][2],     s[2 * kc][3]);
            unsigned a2 = pack2(s[2 * kc + 1][0], s[2 * kc + 1][1]);
            unsigned a3 = pack2(s[2 * kc + 1][2], s[2 * kc + 1][3]);
            #pragma unroll
            for (int dt = 0; dt < 8; dt++) {
                unsigned b0 = *(const unsigned*)&Vt_s[(dt * 8 + tq) * KHP + kc * 16 + 2 * tr];
                unsigned b1 = *(const unsigned*)&Vt_s[(dt * 8 + tq) * KHP + kc * 16 + 2 * tr + 8];
                mma_f16(o[dt], a0, a1, a2, a3, b0, b1);
            }
        }
    }

    float inv0 = 1.f / l0, inv1 = 1.f / l1;
    float* ob = g_ao + (size_t)(b * T_ + qt * 128 + warp * 16) * C_ + h * HD;
    #pragma unroll
    for (int nt = 0; nt < 8; nt++) {
        *(float2*)&ob[(size_t)tq * C_ + nt * 8 + 2 * tr] =
            make_float2(o[nt][0] * inv0, o[nt][1] * inv0);
        *(float2*)&ob[(size_t)(tq + 8) * C_ + nt * 8 + 2 * tr] =
            make_float2(o[nt][2] * inv1, o[nt][3] * inv1);
    }
}

// ---------------- launch ----------------
extern "C" void kernel_launch(void* const* d_in, const int* in_sizes, int n_in,
                              void* d_out, int out_size) {
    const float* x    = (const float*)d_in[0];
    const float* kc   = (const float*)d_in[1];
    const float* vc   = (const float*)d_in[2];
    const int*   pidx = (const int*)  d_in[3];
    const float* Wq   = (const float*)d_in[4];
    const float* Wk   = (const float*)d_in[5];
    const float* Wv   = (const float*)d_in[6];
    const float* Wo   = (const float*)d_in[7];

    float* out  = (float*)d_out;
    float* kout = out + 2 * 1024 * 1024;
    float* vout = kout + 2 * 4 * 2048 * 64;

    float* gao;
    cudaGetSymbolAddress((void**)&gao, g_ao);

    cudaFuncSetAttribute(qkv_gemm, cudaFuncAttributeMaxDynamicSharedMemorySize, GSM);
    cudaFuncSetAttribute(o_gemm,   cudaFuncAttributeMaxDynamicSharedMemorySize, GSM);
    cudaFuncSetAttribute(attn_h,   cudaFuncAttributeMaxDynamicSharedMemorySize, AHSM);

    rope_tab<<<(ROWS * 32) / 256, 256>>>(pidx);               // launch 0

    dim3 gqkv(24, 16);
    qkv_gemm<<<gqkv, 128, GSM>>>(x, Wq, Wk, Wv, kout, vout);  // launch 1

    int nc = B_ * NKV * 1024 * 16;
    copy_cache<<<(nc + 255) / 256, 256>>>(kc, vc, kout, vout);// launch 2

    dim3 ga(T_ / 128, NH, B_);                                // (8,16,2)
    attn_h<<<ga, 256, AHSM>>>();                              // launch 3 (profiled)

    dim3 go(16, 16);
    o_gemm<<<go, 128, GSM>>>(gao, Wo, out);                   // launch 4
}

// round 9
// speedup vs baseline: 2.0611x; 1.1157x over previous
#include <cuda_runtime.h>
#include <cuda_fp16.h>
#include <math.h>
#include <stdint.h>

#define B_   2
#define T_   1024
#define C_   1024
#define NH   16
#define NKV  4
#define HD   64
#define S_   2048
#define ROWS 2048

// q scale: 1/8 (attn scale) * log2(e)  (so P = 2^S = e^(q.k/8))
#define QSCALE 0.18033688011112042f

// ---------------- scratch ----------------
__device__ float  g_ao[ROWS * C_];
__device__ float  g_cos[ROWS * 32];
__device__ float  g_sin[ROWS * 32];
__device__ __half g_qh [ROWS * C_];        // q * QSCALE, roped, half
__device__ __half g_kh [8 * S_ * HD];      // K half, [bk][s][d]
__device__ __half g_vTh[8 * HD * S_];      // V^T half, [bk][d][s]

// ---------------- helpers ----------------
__device__ __forceinline__ unsigned f2tf(float x) {
    unsigned u;
    asm("cvt.rna.tf32.f32 %0, %1;" : "=r"(u) : "f"(x));
    return u;
}
__device__ __forceinline__ unsigned pack2(float lo, float hi) {
    unsigned u;
    asm("cvt.rn.f16x2.f32 %0, %1, %2;" : "=r"(u) : "f"(hi), "f"(lo));
    return u;
}
__device__ __forceinline__ unsigned hexp2(unsigned x) {
    unsigned u;
    asm("ex2.approx.f16x2 %0, %1;" : "=r"(u) : "r"(x));
    return u;
}
__device__ __forceinline__ void mma_tf32(float* c,
                                         unsigned a0, unsigned a1, unsigned a2, unsigned a3,
                                         unsigned b0, unsigned b1) {
    asm volatile(
        "mma.sync.aligned.m16n8k8.row.col.f32.tf32.tf32.f32 "
        "{%0,%1,%2,%3}, {%4,%5,%6,%7}, {%8,%9}, {%0,%1,%2,%3};"
        : "+f"(c[0]), "+f"(c[1]), "+f"(c[2]), "+f"(c[3])
        : "r"(a0), "r"(a1), "r"(a2), "r"(a3), "r"(b0), "r"(b1));
}
__device__ __forceinline__ void mma_f16(float* c,
                                        unsigned a0, unsigned a1, unsigned a2, unsigned a3,
                                        unsigned b0, unsigned b1) {
    asm volatile(
        "mma.sync.aligned.m16n8k16.row.col.f32.f16.f16.f32 "
        "{%0,%1,%2,%3}, {%4,%5,%6,%7}, {%8,%9}, {%0,%1,%2,%3};"
        : "+f"(c[0]), "+f"(c[1]), "+f"(c[2]), "+f"(c[3])
        : "r"(a0), "r"(a1), "r"(a2), "r"(a3), "r"(b0), "r"(b1));
}
__device__ __forceinline__ void cpa16(unsigned s, const void* g) {
    asm volatile("cp.async.ca.shared.global [%0], [%1], 16;" :: "r"(s), "l"(g));
}
__device__ __forceinline__ void cpa_commit() { asm volatile("cp.async.commit_group;"); }

// ---------------- GEMM core (tf32, unchanged) ----------------
#define AS 36
#define BS 72
#define GSM ((2*128*AS + 2*32*BS) * 4)

__device__ __forceinline__ void gemm_main(const float* __restrict__ A,
                                          const float* __restrict__ Bw,
                                          int ldB, int m0, int n0,
                                          float acc[2][8][4], float* smf) {
    float* A_s = smf;
    float* B_s = smf + 2 * 128 * AS;
    const int tid = threadIdx.x;
    unsigned aBase = (unsigned)__cvta_generic_to_shared(A_s);
    unsigned bBase = (unsigned)__cvta_generic_to_shared(B_s);
    const int arow = tid >> 3, ac4 = (tid & 7) << 2;
    const int brow = tid >> 4, bc4 = (tid & 15) << 2;

    #pragma unroll
    for (int i = 0; i < 8; i++)
        cpa16(aBase + (((arow + i * 16) * AS + ac4) << 2),
              &A[(size_t)(m0 + arow + i * 16) * 1024 + ac4]);
    #pragma unroll
    for (int i = 0; i < 4; i++)
        cpa16(bBase + (((brow + i * 8) * BS + bc4) << 2),
              &Bw[(size_t)(brow + i * 8) * ldB + n0 + bc4]);
    cpa_commit();

    const int lane = tid & 31, warp = tid >> 5;
    const int tq = lane >> 2, tr = lane & 3;
    int buf = 0;
    for (int c = 0; c < 32; c++) {
        if (c < 31) {
            int kc = (c + 1) * 32;
            int nb = buf ^ 1;
            #pragma unroll
            for (int i = 0; i < 8; i++)
                cpa16(aBase + ((((nb * 128) + arow + i * 16) * AS + ac4) << 2),
                      &A[(size_t)(m0 + arow + i * 16) * 1024 + kc + ac4]);
            #pragma unroll
            for (int i = 0; i < 4; i++)
                cpa16(bBase + ((((nb * 32) + brow + i * 8) * BS + bc4) << 2),
                      &Bw[(size_t)(kc + brow + i * 8) * ldB + n0 + bc4]);
            cpa_commit();
            asm volatile("cp.async.wait_group 1;");
        } else {
            asm volatile("cp.async.wait_group 0;");
        }
        __syncthreads();

        const float* Ab = A_s + buf * 128 * AS;
        const float* Bb = B_s + buf * 32 * BS;
        #pragma unroll
        for (int ks = 0; ks < 4; ks++) {
            unsigned a[2][4];
            #pragma unroll
            for (int mt = 0; mt < 2; mt++) {
                const float* p = &Ab[(warp * 32 + mt * 16 + tq) * AS + ks * 8 + tr];
                a[mt][0] = f2tf(p[0]);
                a[mt][1] = f2tf(p[8 * AS]);
                a[mt][2] = f2tf(p[4]);
                a[mt][3] = f2tf(p[8 * AS + 4]);
            }
            #pragma unroll
            for (int nt = 0; nt < 8; nt++) {
                unsigned b0 = f2tf(Bb[(ks * 8 + tr) * BS + nt * 8 + tq]);
                unsigned b1 = f2tf(Bb[(ks * 8 + tr + 4) * BS + nt * 8 + tq]);
                mma_tf32(acc[0][nt], a[0][0], a[0][1], a[0][2], a[0][3], b0, b1);
                mma_tf32(acc[1][nt], a[1][0], a[1][1], a[1][2], a[1][3], b0, b1);
            }
        }
        __syncthreads();
        buf ^= 1;
    }
}

__device__ __forceinline__ void rope_acc(float acc[2][8][4], int m0) {
    const int lane = threadIdx.x & 31, warp = threadIdx.x >> 5;
    const int tq = lane >> 2, tr = lane & 3;
    #pragma unroll
    for (int mt = 0; mt < 2; mt++) {
        int r0 = m0 + warp * 32 + mt * 16 + tq;
        int r1 = r0 + 8;
        #pragma unroll
        for (int nt = 0; nt < 4; nt++) {
            int i0 = nt * 8 + 2 * tr;
            float2 c0 = *(const float2*)&g_cos[r0 * 32 + i0];
            float2 s0 = *(const float2*)&g_sin[r0 * 32 + i0];
            float2 c1 = *(const float2*)&g_cos[r1 * 32 + i0];
            float2 s1 = *(const float2*)&g_sin[r1 * 32 + i0];
            float x1, x2;
            x1 = acc[mt][nt][0]; x2 = acc[mt][nt + 4][0];
            acc[mt][nt][0] = x1 * c0.x - x2 * s0.x;  acc[mt][nt + 4][0] = x2 * c0.x + x1 * s0.x;
            x1 = acc[mt][nt][1]; x2 = acc[mt][nt + 4][1];
            acc[mt][nt][1] = x1 * c0.y - x2 * s0.y;  acc[mt][nt + 4][1] = x2 * c0.y + x1 * s0.y;
            x1 = acc[mt][nt][2]; x2 = acc[mt][nt + 4][2];
            acc[mt][nt][2] = x1 * c1.x - x2 * s1.x;  acc[mt][nt + 4][2] = x2 * c1.x + x1 * s1.x;
            x1 = acc[mt][nt][3]; x2 = acc[mt][nt + 4][3];
            acc[mt][nt][3] = x1 * c1.y - x2 * s1.y;  acc[mt][nt + 4][3] = x2 * c1.y + x1 * s1.y;
        }
    }
}

// ---------------- merged QKV projection (+rope, +scatter, +half side copies) ----------------
__global__ __launch_bounds__(128, 4) void qkv_gemm(const float* __restrict__ x,
                                                   const float* __restrict__ Wq,
                                                   const float* __restrict__ Wk,
                                                   const float* __restrict__ Wv,
                                                   float* __restrict__ kout,
                                                   float* __restrict__ vout) {
    extern __shared__ float smf[];
    const int bx = blockIdx.x, m0 = blockIdx.y * 128;
    const float* Bw; int ldB, n0, mode;
    if (bx < 16)      { Bw = Wq; ldB = 1024; n0 = bx * 64;        mode = 0; }
    else if (bx < 20) { Bw = Wk; ldB = 256;  n0 = (bx - 16) * 64; mode = 1; }
    else              { Bw = Wv; ldB = 256;  n0 = (bx - 20) * 64; mode = 2; }

    float acc[2][8][4];
    #pragma unroll
    for (int i = 0; i < 2; i++)
        #pragma unroll
        for (int j = 0; j < 8; j++)
            #pragma unroll
            for (int k = 0; k < 4; k++) acc[i][j][k] = 0.f;

    gemm_main(x, Bw, ldB, m0, n0, acc, smf);
    if (mode != 2) rope_acc(acc, m0);

    const int lane = threadIdx.x & 31, warp = threadIdx.x >> 5;
    const int tq = lane >> 2, tr = lane & 3;
    #pragma unroll
    for (int mt = 0; mt < 2; mt++) {
        int r = m0 + warp * 32 + mt * 16 + tq;
        if (mode == 0) {
            __half* p0 = &g_qh[(size_t)r * C_ + n0];
            __half* p1 = &g_qh[(size_t)(r + 8) * C_ + n0];
            #pragma unroll
            for (int nt = 0; nt < 8; nt++) {
                *(unsigned*)&p0[nt * 8 + 2 * tr] =
                    pack2(acc[mt][nt][0] * QSCALE, acc[mt][nt][1] * QSCALE);
                *(unsigned*)&p1[nt * 8 + 2 * tr] =
                    pack2(acc[mt][nt][2] * QSCALE, acc[mt][nt][3] * QSCALE);
            }
        } else {
            int b = r >> 10, t = r & 1023;
            int kv = (mode == 1) ? (bx - 16) : (bx - 20);
            int bk = b * NKV + kv;
            float* dst = (mode == 1) ? kout : vout;
            float* p0 = &dst[(size_t)(bk * S_ + 1024 + t) * HD];
            float* p1 = &dst[(size_t)(bk * S_ + 1024 + t + 8) * HD];
            #pragma unroll
            for (int nt = 0; nt < 8; nt++) {
                *(float2*)&p0[nt * 8 + 2 * tr] = make_float2(acc[mt][nt][0], acc[mt][nt][1]);
                *(float2*)&p1[nt * 8 + 2 * tr] = make_float2(acc[mt][nt][2], acc[mt][nt][3]);
            }
            if (mode == 1) {
                __half* q0 = &g_kh[(size_t)(bk * S_ + 1024 + t) * HD];
                __half* q1 = &g_kh[(size_t)(bk * S_ + 1024 + t + 8) * HD];
                #pragma unroll
                for (int nt = 0; nt < 8; nt++) {
                    *(unsigned*)&q0[nt * 8 + 2 * tr] = pack2(acc[mt][nt][0], acc[mt][nt][1]);
                    *(unsigned*)&q1[nt * 8 + 2 * tr] = pack2(acc[mt][nt][2], acc[mt][nt][3]);
                }
            } else {
                __half* vt = g_vTh + (size_t)bk * HD * S_;
                #pragma unroll
                for (int nt = 0; nt < 8; nt++) {
                    int d = nt * 8 + 2 * tr;
                    vt[(size_t)d * S_ + 1024 + t]           = __float2half_rn(acc[mt][nt][0]);
                    vt[(size_t)(d + 1) * S_ + 1024 + t]     = __float2half_rn(acc[mt][nt][1]);
                    vt[(size_t)d * S_ + 1024 + t + 8]       = __float2half_rn(acc[mt][nt][2]);
                    vt[(size_t)(d + 1) * S_ + 1024 + t + 8] = __float2half_rn(acc[mt][nt][3]);
                }
            }
        }
    }
}

// ---------------- O projection (tf32) ----------------
__global__ __launch_bounds__(128, 4) void o_gemm(const float* __restrict__ A,
                                                 const float* __restrict__ Wo,
                                                 float* __restrict__ out) {
    extern __shared__ float smf[];
    const int m0 = blockIdx.y * 128, n0 = blockIdx.x * 64;
    float acc[2][8][4];
    #pragma unroll
    for (int i = 0; i < 2; i++)
        #pragma unroll
        for (int j = 0; j < 8; j++)
            #pragma unroll
            for (int k = 0; k < 4; k++) acc[i][j][k] = 0.f;

    gemm_main(A, Wo, 1024, m0, n0, acc, smf);

    const int lane = threadIdx.x & 31, warp = threadIdx.x >> 5;
    const int tq = lane >> 2, tr = lane & 3;
    #pragma unroll
    for (int mt = 0; mt < 2; mt++) {
        int r = m0 + warp * 32 + mt * 16 + tq;
        float* p0 = &out[(size_t)r * C_ + n0];
        float* p1 = &out[(size_t)(r + 8) * C_ + n0];
        #pragma unroll
        for (int nt = 0; nt < 8; nt++) {
            *(float2*)&p0[nt * 8 + 2 * tr] = make_float2(acc[mt][nt][0], acc[mt][nt][1]);
            *(float2*)&p1[nt * 8 + 2 * tr] = make_float2(acc[mt][nt][2], acc[mt][nt][3]);
        }
    }
}

// ---------------- rope tables ----------------
__global__ void rope_tab(const int* __restrict__ pidx) {
    __shared__ float invf[32];
    if (threadIdx.x < 32)
        invf[threadIdx.x] = (float)pow(10000.0, -(double)threadIdx.x / 32.0);
    __syncthreads();
    int idx = blockIdx.x * blockDim.x + threadIdx.x;
    if (idx >= ROWS * 32) return;
    int i = idx & 31, row = idx >> 5;
    int p = min(max(pidx[row] + (row & 1023) + 1024, 0), 4095);
    float ang = (float)p * invf[i];
    float c, s;
    sincosf(ang, &s, &c);
    g_cos[idx] = c;
    g_sin[idx] = s;
}

// ---------------- cache halves copy (+half side copies) ----------------
__global__ void copy_cache(const float* __restrict__ kc, const float* __restrict__ vc,
                           float* __restrict__ kout, float* __restrict__ vout) {
    int idx = blockIdx.x * blockDim.x + threadIdx.x;
    if (idx >= B_ * NKV * 1024 * 16) return;
    int d4 = idx & 15;
    int s  = (idx >> 4) & 1023;
    int bk = idx >> 14;
    int dst = ((bk * S_) + s) * 16 + d4;
    float4 kq = ((const float4*)kc)[idx];
    float4 vq = ((const float4*)vc)[idx];
    ((float4*)kout)[dst] = kq;
    ((float4*)vout)[dst] = vq;
    __half* kh = &g_kh[(size_t)dst * 4];
    *(unsigned*)&kh[0] = pack2(kq.x, kq.y);
    *(unsigned*)&kh[2] = pack2(kq.z, kq.w);
    __half* vt = g_vTh + (size_t)bk * HD * S_;
    int d0 = d4 * 4;
    vt[(size_t)d0 * S_ + s]       = __float2half_rn(vq.x);
    vt[(size_t)(d0 + 1) * S_ + s] = __float2half_rn(vq.y);
    vt[(size_t)(d0 + 2) * S_ + s] = __float2half_rn(vq.z);
    vt[(size_t)(d0 + 3) * S_ + s] = __float2half_rn(vq.w);
}

// ---------------- Flash attention v9: fp16, no-max softmax, ex2.f16x2, ones-mma l,
//                  cp.async double-buffered K/V ----------------
#define KHP  72
#define HBUF (2 * 64 * KHP)              // halves per buffer (K + V^T)
#define AHSM (2 * HBUF * 2)              // 36864 B
#define ONES 0x3C003C00u

__global__ __launch_bounds__(256, 2) void attn_h() {
    extern __shared__ __half smh[];
    const unsigned sBase = (unsigned)__cvta_generic_to_shared(smh);

    const int tid = threadIdx.x, lane = tid & 31, warp = tid >> 5;
    const int tq = lane >> 2, tr = lane & 3;
    const int qt = blockIdx.x, h = blockIdx.y, b = blockIdx.z;
    const int bk = b * NKV + (h >> 2);
    const __half* kh  = g_kh  + (size_t)bk * S_ * HD;
    const __half* vth = g_vTh + (size_t)bk * HD * S_;
    const __half* qh  = g_qh  + (size_t)(b * T_ + qt * 128 + warp * 16) * C_ + h * HD;

    // fill indices: 1024 cpa16 per buffer (512 K + 512 V), 4 per thread
    const int frow = (tid >> 3) & 31;            // used with +32 offset below
    const int fj8  = (tid & 7) * 8;

    // prologue: chunk 0 -> buf 0
    {
        #pragma unroll
        for (int p = 0; p < 2; p++) {
            int row = frow + p * 32;
            cpa16(sBase + ((row * KHP + fj8) << 1), &kh[(size_t)row * HD + fj8]);
            cpa16(sBase + ((64 * KHP + row * KHP + fj8) << 1), &vth[(size_t)row * S_ + fj8]);
        }
        cpa_commit();
    }

    // Q fragments (half2), resident all kernel
    unsigned qa[4][4];
    #pragma unroll
    for (int kc = 0; kc < 4; kc++) {
        qa[kc][0] = *(const unsigned*)&qh[(size_t)tq * C_ + kc * 16 + 2 * tr];
        qa[kc][1] = *(const unsigned*)&qh[(size_t)(tq + 8) * C_ + kc * 16 + 2 * tr];
        qa[kc][2] = *(const unsigned*)&qh[(size_t)tq * C_ + kc * 16 + 2 * tr + 8];
        qa[kc][3] = *(const unsigned*)&qh[(size_t)(tq + 8) * C_ + kc * 16 + 2 * tr + 8];
    }

    float o[8][4];
    #pragma unroll
    for (int nt = 0; nt < 8; nt++)
        #pragma unroll
        for (int k = 0; k < 4; k++) o[nt][k] = 0.f;
    float lacc[4] = {0.f, 0.f, 0.f, 0.f};

    for (int c = 0; c < 32; c++) {
        asm volatile("cp.async.wait_group 0;");
        __syncthreads();                         // buf[c&1] ready, visible to all

        // prefetch chunk c+1 into the other buffer (its readers finished at end of c-1)
        if (c + 1 < 32) {
            int c0 = (c + 1) * 64;
            unsigned base = sBase + (unsigned)(((c + 1) & 1) * HBUF * 2);
            #pragma unroll
            for (int p = 0; p < 2; p++) {
                int row = frow + p * 32;
                cpa16(base + ((row * KHP + fj8) << 1), &kh[(size_t)(c0 + row) * HD + fj8]);
                cpa16(base + ((64 * KHP + row * KHP + fj8) << 1),
                      &vth[(size_t)row * S_ + c0 + fj8]);
            }
            cpa_commit();
        }

        const __half* K_s  = smh + (c & 1) * HBUF;
        const __half* Vt_s = K_s + 64 * KHP;

        // S = Q @ K^T  (log2-space scores)
        float s[8][4];
        #pragma unroll
        for (int nt = 0; nt < 8; nt++)
            #pragma unroll
            for (int k = 0; k < 4; k++) s[nt][k] = 0.f;
        #pragma unroll
        for (int kc = 0; kc < 4; kc++)
            #pragma unroll
            for (int nt = 0; nt < 8; nt++) {
                unsigned b0 = *(const unsigned*)&K_s[(nt * 8 + tq) * KHP + kc * 16 + 2 * tr];
                unsigned b1 = *(const unsigned*)&K_s[(nt * 8 + tq) * KHP + kc * 16 + 2 * tr + 8];
                mma_f16(s[nt], qa[kc][0], qa[kc][1], qa[kc][2], qa[kc][3], b0, b1);
            }

        // P = 2^S (f16x2), l += P @ ones, O += P @ V  — no max, no rescale
        #pragma unroll
        for (int kc = 0; kc < 4; kc++) {
            unsigned a0 = hexp2(pack2(s[2 * kc][0],     s[2 * kc][1]));
            unsigned a1 = hexp2(pack2(s[2 * kc][2],     s[2 * kc][3]));
            unsigned a2 = hexp2(pack2(s[2 * kc + 1][0], s[2 * kc + 1][1]));
            unsigned a3 = hexp2(pack2(s[2 * kc + 1][2], s[2 * kc + 1][3]));
            mma_f16(lacc, a0, a1, a2, a3, ONES, ONES);
            #pragma unroll
            for (int dt = 0; dt < 8; dt++) {
                unsigned b0 = *(const unsigned*)&Vt_s[(dt * 8 + tq) * KHP + kc * 16 + 2 * tr];
                unsigned b1 = *(const unsigned*)&Vt_s[(dt * 8 + tq) * KHP + kc * 16 + 2 * tr + 8];
                mma_f16(o[dt], a0, a1, a2, a3, b0, b1);
            }
        }
        __syncthreads();                         // all reads of buf[c&1] done
    }

    float inv0 = 1.f / lacc[0], inv1 = 1.f / lacc[2];
    float* ob = g_ao + (size_t)(b * T_ + qt * 128 + warp * 16) * C_ + h * HD;
    #pragma unroll
    for (int nt = 0; nt < 8; nt++) {
        *(float2*)&ob[(size_t)tq * C_ + nt * 8 + 2 * tr] =
            make_float2(o[nt][0] * inv0, o[nt][1] * inv0);
        *(float2*)&ob[(size_t)(tq + 8) * C_ + nt * 8 + 2 * tr] =
            make_float2(o[nt][2] * inv1, o[nt][3] * inv1);
    }
}

// ---------------- launch ----------------
extern "C" void kernel_launch(void* const* d_in, const int* in_sizes, int n_in,
                              void* d_out, int out_size) {
    const float* x    = (const float*)d_in[0];
    const float* kc   = (const float*)d_in[1];
    const float* vc   = (const float*)d_in[2];
    const int*   pidx = (const int*)  d_in[3];
    const float* Wq   = (const float*)d_in[4];
    const float* Wk   = (const float*)d_in[5];
    const float* Wv   = (const float*)d_in[6];
    const float* Wo   = (const float*)d_in[7];

    float* out  = (float*)d_out;
    float* kout = out + 2 * 1024 * 1024;
    float* vout = kout + 2 * 4 * 2048 * 64;

    float* gao;
    cudaGetSymbolAddress((void**)&gao, g_ao);

    cudaFuncSetAttribute(qkv_gemm, cudaFuncAttributeMaxDynamicSharedMemorySize, GSM);
    cudaFuncSetAttribute(o_gemm,   cudaFuncAttributeMaxDynamicSharedMemorySize, GSM);
    cudaFuncSetAttribute(attn_h,   cudaFuncAttributeMaxDynamicSharedMemorySize, AHSM);

    rope_tab<<<(ROWS * 32) / 256, 256>>>(pidx);               // launch 0

    dim3 gqkv(24, 16);
    qkv_gemm<<<gqkv, 128, GSM>>>(x, Wq, Wk, Wv, kout, vout);  // launch 1

    int nc = B_ * NKV * 1024 * 16;
    copy_cache<<<(nc + 255) / 256, 256>>>(kc, vc, kout, vout);// launch 2

    dim3 ga(T_ / 128, NH, B_);                                // (8,16,2)
    attn_h<<<ga, 256, AHSM>>>();                              // launch 3 (profiled)

    dim3 go(16, 16);
    o_gemm<<<go, 128, GSM>>>(gao, Wo, out);                   // launch 4
}

// round 10
// speedup vs baseline: 2.5504x; 1.2374x over previous
#include <cuda_runtime.h>
#include <cuda_fp16.h>
#include <math.h>
#include <stdint.h>

#define B_   2
#define T_   1024
#define C_   1024
#define NH   16
#define NKV  4
#define HD   64
#define S_   2048
#define ROWS 2048

// q scale: 1/8 (attn scale) * log2(e)  (so P = 2^S = e^(q.k/8))
#define QSCALE 0.18033688011112042f

// ---------------- scratch ----------------
__device__ float  g_cos[ROWS * 32];
__device__ float  g_sin[ROWS * 32];
__device__ __half g_xh [ROWS * C_];        // x in half
__device__ __half g_qh [ROWS * C_];        // q * QSCALE, roped
__device__ __half g_kh [8 * S_ * HD];      // K half, [bk][s][d]
__device__ __half g_vTh[8 * HD * S_];      // V^T half, [bk][d][s]
__device__ __half g_aoh[ROWS * C_];        // attention out, half
__device__ __half g_WqT[C_ * C_];          // W^T halves: [n][k]
__device__ __half g_WkT[256 * C_];
__device__ __half g_WvT[256 * C_];
__device__ __half g_WoT[C_ * C_];

// ---------------- helpers ----------------
__device__ __forceinline__ unsigned pack2(float lo, float hi) {
    unsigned u;
    asm("cvt.rn.f16x2.f32 %0, %1, %2;" : "=r"(u) : "f"(hi), "f"(lo));
    return u;
}
__device__ __forceinline__ unsigned hexp2(unsigned x) {
    unsigned u;
    asm("ex2.approx.f16x2 %0, %1;" : "=r"(u) : "r"(x));
    return u;
}
__device__ __forceinline__ void mma_f16(float* c,
                                        unsigned a0, unsigned a1, unsigned a2, unsigned a3,
                                        unsigned b0, unsigned b1) {
    asm volatile(
        "mma.sync.aligned.m16n8k16.row.col.f32.f16.f16.f32 "
        "{%0,%1,%2,%3}, {%4,%5,%6,%7}, {%8,%9}, {%0,%1,%2,%3};"
        : "+f"(c[0]), "+f"(c[1]), "+f"(c[2]), "+f"(c[3])
        : "r"(a0), "r"(a1), "r"(a2), "r"(a3), "r"(b0), "r"(b1));
}
__device__ __forceinline__ void cpa16(unsigned s, const void* g) {
    asm volatile("cp.async.ca.shared.global [%0], [%1], 16;" :: "r"(s), "l"(g));
}
__device__ __forceinline__ void cpa_commit() { asm volatile("cp.async.commit_group;"); }
__device__ __forceinline__ void ldsm4(unsigned* r, unsigned addr) {
    asm volatile("ldmatrix.sync.aligned.m8n8.x4.shared.b16 {%0,%1,%2,%3}, [%4];"
        : "=r"(r[0]), "=r"(r[1]), "=r"(r[2]), "=r"(r[3]) : "r"(addr));
}

// ---------------- fp16 GEMM core: 128M x 64N, 128 thr, K=1024, chunk 64, cp.async x2 ----
#define HS 72                                   // half stride per row
#define GSM ((2*128*HS + 2*64*HS) * 2)          // 55296 B

__device__ __forceinline__ void gemm_h(const __half* __restrict__ A,
                                       const __half* __restrict__ BT,
                                       int m0, int n0,
                                       float acc[2][8][4], __half* smh) {
    const int tid = threadIdx.x, lane = tid & 31, warp = tid >> 5;
    unsigned aB = (unsigned)__cvta_generic_to_shared(smh);
    unsigned bB = aB + 2 * 128 * HS * 2;

    // prologue: chunk 0 -> buf 0
    #pragma unroll
    for (int i = 0; i < 8; i++) {
        int idx = tid + i * 128, row = idx >> 3, j = idx & 7;
        cpa16(aB + ((row * HS + j * 8) << 1), &A[(size_t)(m0 + row) * 1024 + j * 8]);
    }
    #pragma unroll
    for (int i = 0; i < 4; i++) {
        int idx = tid + i * 128, row = idx >> 3, j = idx & 7;
        cpa16(bB + ((row * HS + j * 8) << 1), &BT[(size_t)(n0 + row) * 1024 + j * 8]);
    }
    cpa_commit();

    // ldmatrix per-lane address components
    const int aRow = ((lane >> 3) & 1) * 8 + (lane & 7);   // within 16-row A frag
    const int aCol = (lane >> 4) * 8;                      // k sub-tile
    const int bRow = (lane >> 4) * 8 + (lane & 7);         // within 16-row B pair
    const int bCol = ((lane >> 3) & 1) * 8;

    int buf = 0;
    for (int c = 0; c < 16; c++) {
        if (c < 15) {
            int kc = (c + 1) * 64, nb = buf ^ 1;
            #pragma unroll
            for (int i = 0; i < 8; i++) {
                int idx = tid + i * 128, row = idx >> 3, j = idx & 7;
                cpa16(aB + (((nb * 128 + row) * HS + j * 8) << 1),
                      &A[(size_t)(m0 + row) * 1024 + kc + j * 8]);
            }
            #pragma unroll
            for (int i = 0; i < 4; i++) {
                int idx = tid + i * 128, row = idx >> 3, j = idx & 7;
                cpa16(bB + (((nb * 64 + row) * HS + j * 8) << 1),
                      &BT[(size_t)(n0 + row) * 1024 + kc + j * 8]);
            }
            cpa_commit();
            asm volatile("cp.async.wait_group 1;");
        } else {
            asm volatile("cp.async.wait_group 0;");
        }
        __syncthreads();

        unsigned Ab = aB + (unsigned)(buf * 128 * HS * 2);
        unsigned Bb = bB + (unsigned)(buf * 64 * HS * 2);
        #pragma unroll
        for (int ks = 0; ks < 4; ks++) {
            unsigned a[2][4];
            #pragma unroll
            for (int mt = 0; mt < 2; mt++)
                ldsm4(a[mt], Ab + (((warp * 32 + mt * 16 + aRow) * HS + ks * 16 + aCol) << 1));
            #pragma unroll
            for (int ntp = 0; ntp < 4; ntp++) {
                unsigned bb[4];
                ldsm4(bb, Bb + (((ntp * 16 + bRow) * HS + ks * 16 + bCol) << 1));
                mma_f16(acc[0][2 * ntp],     a[0][0], a[0][1], a[0][2], a[0][3], bb[0], bb[1]);
                mma_f16(acc[0][2 * ntp + 1], a[0][0], a[0][1], a[0][2], a[0][3], bb[2], bb[3]);
                mma_f16(acc[1][2 * ntp],     a[1][0], a[1][1], a[1][2], a[1][3], bb[0], bb[1]);
                mma_f16(acc[1][2 * ntp + 1], a[1][0], a[1][1], a[1][2], a[1][3], bb[2], bb[3]);
            }
        }
        __syncthreads();
        buf ^= 1;
    }
}

// rope rotate in registers: pairs (nt, nt+4)
__device__ __forceinline__ void rope_acc(float acc[2][8][4], int m0) {
    const int lane = threadIdx.x & 31, warp = threadIdx.x >> 5;
    const int tq = lane >> 2, tr = lane & 3;
    #pragma unroll
    for (int mt = 0; mt < 2; mt++) {
        int r0 = m0 + warp * 32 + mt * 16 + tq;
        int r1 = r0 + 8;
        #pragma unroll
        for (int nt = 0; nt < 4; nt++) {
            int i0 = nt * 8 + 2 * tr;
            float2 c0 = *(const float2*)&g_cos[r0 * 32 + i0];
            float2 s0 = *(const float2*)&g_sin[r0 * 32 + i0];
            float2 c1 = *(const float2*)&g_cos[r1 * 32 + i0];
            float2 s1 = *(const float2*)&g_sin[r1 * 32 + i0];
            float x1, x2;
            x1 = acc[mt][nt][0]; x2 = acc[mt][nt + 4][0];
            acc[mt][nt][0] = x1 * c0.x - x2 * s0.x;  acc[mt][nt + 4][0] = x2 * c0.x + x1 * s0.x;
            x1 = acc[mt][nt][1]; x2 = acc[mt][nt + 4][1];
            acc[mt][nt][1] = x1 * c0.y - x2 * s0.y;  acc[mt][nt + 4][1] = x2 * c0.y + x1 * s0.y;
            x1 = acc[mt][nt][2]; x2 = acc[mt][nt + 4][2];
            acc[mt][nt][2] = x1 * c1.x - x2 * s1.x;  acc[mt][nt + 4][2] = x2 * c1.x + x1 * s1.x;
            x1 = acc[mt][nt][3]; x2 = acc[mt][nt + 4][3];
            acc[mt][nt][3] = x1 * c1.y - x2 * s1.y;  acc[mt][nt + 4][3] = x2 * c1.y + x1 * s1.y;
        }
    }
}

// ---------------- merged QKV projection (+rope, +scatter, +half side copies) ----------------
__global__ __launch_bounds__(128, 4) void qkv_gemm(float* __restrict__ kout,
                                                   float* __restrict__ vout) {
    extern __shared__ __half smh[];
    const int bx = blockIdx.x, m0 = blockIdx.y * 128;
    const __half* BT; int n0, mode;
    if (bx < 16)      { BT = g_WqT; n0 = bx * 64;        mode = 0; }
    else if (bx < 20) { BT = g_WkT; n0 = (bx - 16) * 64; mode = 1; }
    else              { BT = g_WvT; n0 = (bx - 20) * 64; mode = 2; }

    float acc[2][8][4];
    #pragma unroll
    for (int i = 0; i < 2; i++)
        #pragma unroll
        for (int j = 0; j < 8; j++)
            #pragma unroll
            for (int k = 0; k < 4; k++) acc[i][j][k] = 0.f;

    gemm_h(g_xh, BT, m0, n0, acc, smh);
    if (mode != 2) rope_acc(acc, m0);

    const int lane = threadIdx.x & 31, warp = threadIdx.x >> 5;
    const int tq = lane >> 2, tr = lane & 3;
    #pragma unroll
    for (int mt = 0; mt < 2; mt++) {
        int r = m0 + warp * 32 + mt * 16 + tq;
        if (mode == 0) {
            __half* p0 = &g_qh[(size_t)r * C_ + n0];
            __half* p1 = &g_qh[(size_t)(r + 8) * C_ + n0];
            #pragma unroll
            for (int nt = 0; nt < 8; nt++) {
                *(unsigned*)&p0[nt * 8 + 2 * tr] =
                    pack2(acc[mt][nt][0] * QSCALE, acc[mt][nt][1] * QSCALE);
                *(unsigned*)&p1[nt * 8 + 2 * tr] =
                    pack2(acc[mt][nt][2] * QSCALE, acc[mt][nt][3] * QSCALE);
            }
        } else {
            int b = r >> 10, t = r & 1023;
            int kv = (mode == 1) ? (bx - 16) : (bx - 20);
            int bk = b * NKV + kv;
            float* dst = (mode == 1) ? kout : vout;
            float* p0 = &dst[(size_t)(bk * S_ + 1024 + t) * HD];
            float* p1 = &dst[(size_t)(bk * S_ + 1024 + t + 8) * HD];
            #pragma unroll
            for (int nt = 0; nt < 8; nt++) {
                *(float2*)&p0[nt * 8 + 2 * tr] = make_float2(acc[mt][nt][0], acc[mt][nt][1]);
                *(float2*)&p1[nt * 8 + 2 * tr] = make_float2(acc[mt][nt][2], acc[mt][nt][3]);
            }
            if (mode == 1) {
                __half* q0 = &g_kh[(size_t)(bk * S_ + 1024 + t) * HD];
                __half* q1 = &g_kh[(size_t)(bk * S_ + 1024 + t + 8) * HD];
                #pragma unroll
                for (int nt = 0; nt < 8; nt++) {
                    *(unsigned*)&q0[nt * 8 + 2 * tr] = pack2(acc[mt][nt][0], acc[mt][nt][1]);
                    *(unsigned*)&q1[nt * 8 + 2 * tr] = pack2(acc[mt][nt][2], acc[mt][nt][3]);
                }
            } else {
                __half* vt = g_vTh + (size_t)bk * HD * S_;
                #pragma unroll
                for (int nt = 0; nt < 8; nt++) {
                    int d = nt * 8 + 2 * tr;
                    vt[(size_t)d * S_ + 1024 + t]           = __float2half_rn(acc[mt][nt][0]);
                    vt[(size_t)(d + 1) * S_ + 1024 + t]     = __float2half_rn(acc[mt][nt][1]);
                    vt[(size_t)d * S_ + 1024 + t + 8]       = __float2half_rn(acc[mt][nt][2]);
                    vt[(size_t)(d + 1) * S_ + 1024 + t + 8] = __float2half_rn(acc[mt][nt][3]);
                }
            }
        }
    }
}

// ---------------- O projection (fp16) ----------------
__global__ __launch_bounds__(128, 4) void o_gemm(float* __restrict__ out) {
    extern __shared__ __half smh[];
    const int m0 = blockIdx.y * 128, n0 = blockIdx.x * 64;
    float acc[2][8][4];
    #pragma unroll
    for (int i = 0; i < 2; i++)
        #pragma unroll
        for (int j = 0; j < 8; j++)
            #pragma unroll
            for (int k = 0; k < 4; k++) acc[i][j][k] = 0.f;

    gemm_h(g_aoh, g_WoT, m0, n0, acc, smh);

    const int lane = threadIdx.x & 31, warp = threadIdx.x >> 5;
    const int tq = lane >> 2, tr = lane & 3;
    #pragma unroll
    for (int mt = 0; mt < 2; mt++) {
        int r = m0 + warp * 32 + mt * 16 + tq;
        float* p0 = &out[(size_t)r * C_ + n0];
        float* p1 = &out[(size_t)(r + 8) * C_ + n0];
        #pragma unroll
        for (int nt = 0; nt < 8; nt++) {
            *(float2*)&p0[nt * 8 + 2 * tr] = make_float2(acc[mt][nt][0], acc[mt][nt][1]);
            *(float2*)&p1[nt * 8 + 2 * tr] = make_float2(acc[mt][nt][2], acc[mt][nt][3]);
        }
    }
}

// ---------------- prep: rope tables + x->half + cache copy (one launch) ----------------
// threads: [0,65536) rope, [65536,589824) x conv (float4), [589824,720896) cache copy
__global__ void prep_misc(const int* __restrict__ pidx, const float* __restrict__ x,
                          const float* __restrict__ kc, const float* __restrict__ vc,
                          float* __restrict__ kout, float* __restrict__ vout) {
    __shared__ float invf[32];
    if (threadIdx.x < 32)
        invf[threadIdx.x] = (float)pow(10000.0, -(double)threadIdx.x / 32.0);
    __syncthreads();
    int gid = blockIdx.x * 256 + threadIdx.x;
    if (gid < 65536) {
        int i = gid & 31, row = gid >> 5;
        int p = min(max(pidx[row] + (row & 1023) + 1024, 0), 4095);
        float ang = (float)p * invf[i];
        float c, s;
        sincosf(ang, &s, &c);
        g_cos[gid] = c;
        g_sin[gid] = s;
    } else if (gid < 589824) {
        int i = gid - 65536;
        float4 v = ((const float4*)x)[i];
        ((uint2*)g_xh)[i] = make_uint2(pack2(v.x, v.y), pack2(v.z, v.w));
    } else {
        int idx = gid - 589824;                       // 131072 threads
        int d4 = idx & 15;
        int s  = (idx >> 4) & 1023;
        int bk = idx >> 14;
        int dst = ((bk * S_) + s) * 16 + d4;
        float4 kq = ((const float4*)kc)[idx];
        float4 vq = ((const float4*)vc)[idx];
        ((float4*)kout)[dst] = kq;
        ((float4*)vout)[dst] = vq;
        __half* kh = &g_kh[(size_t)dst * 4];
        *(unsigned*)&kh[0] = pack2(kq.x, kq.y);
        *(unsigned*)&kh[2] = pack2(kq.z, kq.w);
        __half* vt = g_vTh + (size_t)bk * HD * S_;
        int d0 = d4 * 4;
        vt[(size_t)d0 * S_ + s]       = __float2half_rn(vq.x);
        vt[(size_t)(d0 + 1) * S_ + s] = __float2half_rn(vq.y);
        vt[(size_t)(d0 + 2) * S_ + s] = __float2half_rn(vq.z);
        vt[(size_t)(d0 + 3) * S_ + s] = __float2half_rn(vq.w);
    }
}

// ---------------- weight transpose + half convert: W[k][n] -> WT[n][k] ----------------
__global__ void wtrans(const float* __restrict__ Wq, const float* __restrict__ Wk,
                       const float* __restrict__ Wv, const float* __restrict__ Wo) {
    __shared__ float t[32][33];
    const int z = blockIdx.z;
    const float* src; __half* dst; int N;
    if (z == 0)      { src = Wq; dst = g_WqT; N = 1024; }
    else if (z == 1) { src = Wk; dst = g_WkT; N = 256; }
    else if (z == 2) { src = Wv; dst = g_WvT; N = 256; }
    else             { src = Wo; dst = g_WoT; N = 1024; }
    int bx = blockIdx.x, by = blockIdx.y;
    if (bx * 32 >= N) return;
    int tx = threadIdx.x, ty = threadIdx.y;   // (32, 8)
    #pragma unroll
    for (int i = 0; i < 4; i++)
        t[ty + i * 8][tx] = src[(size_t)(by * 32 + ty + i * 8) * N + bx * 32 + tx];
    __syncthreads();
    #pragma unroll
    for (int i = 0; i < 4; i++)
        dst[(size_t)(bx * 32 + ty + i * 8) * 1024 + by * 32 + tx] =
            __float2half_rn(t[tx][ty + i * 8]);
}

// ---------------- Flash attention (R9, unchanged except half output) ----------------
#define KHP  72
#define HBUF (2 * 64 * KHP)
#define AHSM (2 * HBUF * 2)
#define ONES 0x3C003C00u

__global__ __launch_bounds__(256, 2) void attn_h() {
    extern __shared__ __half smh[];
    const unsigned sBase = (unsigned)__cvta_generic_to_shared(smh);

    const int tid = threadIdx.x, lane = tid & 31, warp = tid >> 5;
    const int tq = lane >> 2, tr = lane & 3;
    const int qt = blockIdx.x, h = blockIdx.y, b = blockIdx.z;
    const int bk = b * NKV + (h >> 2);
    const __half* kh  = g_kh  + (size_t)bk * S_ * HD;
    const __half* vth = g_vTh + (size_t)bk * HD * S_;
    const __half* qh  = g_qh  + (size_t)(b * T_ + qt * 128 + warp * 16) * C_ + h * HD;

    const int frow = (tid >> 3) & 31;
    const int fj8  = (tid & 7) * 8;

    {
        #pragma unroll
        for (int p = 0; p < 2; p++) {
            int row = frow + p * 32;
            cpa16(sBase + ((row * KHP + fj8) << 1), &kh[(size_t)row * HD + fj8]);
            cpa16(sBase + ((64 * KHP + row * KHP + fj8) << 1), &vth[(size_t)row * S_ + fj8]);
        }
        cpa_commit();
    }

    unsigned qa[4][4];
    #pragma unroll
    for (int kc = 0; kc < 4; kc++) {
        qa[kc][0] = *(const unsigned*)&qh[(size_t)tq * C_ + kc * 16 + 2 * tr];
        qa[kc][1] = *(const unsigned*)&qh[(size_t)(tq + 8) * C_ + kc * 16 + 2 * tr];
        qa[kc][2] = *(const unsigned*)&qh[(size_t)tq * C_ + kc * 16 + 2 * tr + 8];
        qa[kc][3] = *(const unsigned*)&qh[(size_t)(tq + 8) * C_ + kc * 16 + 2 * tr + 8];
    }

    float o[8][4];
    #pragma unroll
    for (int nt = 0; nt < 8; nt++)
        #pragma unroll
        for (int k = 0; k < 4; k++) o[nt][k] = 0.f;
    float lacc[4] = {0.f, 0.f, 0.f, 0.f};

    for (int c = 0; c < 32; c++) {
        asm volatile("cp.async.wait_group 0;");
        __syncthreads();

        if (c + 1 < 32) {
            int c0 = (c + 1) * 64;
            unsigned base = sBase + (unsigned)(((c + 1) & 1) * HBUF * 2);
            #pragma unroll
            for (int p = 0; p < 2; p++) {
                int row = frow + p * 32;
                cpa16(base + ((row * KHP + fj8) << 1), &kh[(size_t)(c0 + row) * HD + fj8]);
                cpa16(base + ((64 * KHP + row * KHP + fj8) << 1),
                      &vth[(size_t)row * S_ + c0 + fj8]);
            }
            cpa_commit();
        }

        const __half* K_s  = smh + (c & 1) * HBUF;
        const __half* Vt_s = K_s + 64 * KHP;

        float s[8][4];
        #pragma unroll
        for (int nt = 0; nt < 8; nt++)
            #pragma unroll
            for (int k = 0; k < 4; k++) s[nt][k] = 0.f;
        #pragma unroll
        for (int kc = 0; kc < 4; kc++)
            #pragma unroll
            for (int nt = 0; nt < 8; nt++) {
                unsigned b0 = *(const unsigned*)&K_s[(nt * 8 + tq) * KHP + kc * 16 + 2 * tr];
                unsigned b1 = *(const unsigned*)&K_s[(nt * 8 + tq) * KHP + kc * 16 + 2 * tr + 8];
                mma_f16(s[nt], qa[kc][0], qa[kc][1], qa[kc][2], qa[kc][3], b0, b1);
            }

        #pragma unroll
        for (int kc = 0; kc < 4; kc++) {
            unsigned a0 = hexp2(pack2(s[2 * kc][0],     s[2 * kc][1]));
            unsigned a1 = hexp2(pack2(s[2 * kc][2],     s[2 * kc][3]));
            unsigned a2 = hexp2(pack2(s[2 * kc + 1][0], s[2 * kc + 1][1]));
            unsigned a3 = hexp2(pack2(s[2 * kc + 1][2], s[2 * kc + 1][3]));
            mma_f16(lacc, a0, a1, a2, a3, ONES, ONES);
            #pragma unroll
            for (int dt = 0; dt < 8; dt++) {
                unsigned b0 = *(const unsigned*)&Vt_s[(dt * 8 + tq) * KHP + kc * 16 + 2 * tr];
                unsigned b1 = *(const unsigned*)&Vt_s[(dt * 8 + tq) * KHP + kc * 16 + 2 * tr + 8];
                mma_f16(o[dt], a0, a1, a2, a3, b0, b1);
            }
        }
        __syncthreads();
    }

    float inv0 = 1.f / lacc[0], inv1 = 1.f / lacc[2];
    __half* ob = g_aoh + (size_t)(b * T_ + qt * 128 + warp * 16) * C_ + h * HD;
    #pragma unroll
    for (int nt = 0; nt < 8; nt++) {
        *(unsigned*)&ob[(size_t)tq * C_ + nt * 8 + 2 * tr] =
            pack2(o[nt][0] * inv0, o[nt][1] * inv0);
        *(unsigned*)&ob[(size_t)(tq + 8) * C_ + nt * 8 + 2 * tr] =
            pack2(o[nt][2] * inv1, o[nt][3] * inv1);
    }
}

// ---------------- launch ----------------
extern "C" void kernel_launch(void* const* d_in, const int* in_sizes, int n_in,
                              void* d_out, int out_size) {
    const float* x    = (const float*)d_in[0];
    const float* kc   = (const float*)d_in[1];
    const float* vc   = (const float*)d_in[2];
    const int*   pidx = (const int*)  d_in[3];
    const float* Wq   = (const float*)d_in[4];
    const float* Wk   = (const float*)d_in[5];
    const float* Wv   = (const float*)d_in[6];
    const float* Wo   = (const float*)d_in[7];

    float* out  = (float*)d_out;
    float* kout = out + 2 * 1024 * 1024;
    float* vout = kout + 2 * 4 * 2048 * 64;

    cudaFuncSetAttribute(qkv_gemm, cudaFuncAttributeMaxDynamicSharedMemorySize, GSM);
    cudaFuncSetAttribute(o_gemm,   cudaFuncAttributeMaxDynamicSharedMemorySize, GSM);
    cudaFuncSetAttribute(attn_h,   cudaFuncAttributeMaxDynamicSharedMemorySize, AHSM);

    prep_misc<<<2816, 256>>>(pidx, x, kc, vc, kout, vout);        // launch 0

    dim3 wt(32, 8);
    wtrans<<<dim3(32, 32, 4), wt>>>(Wq, Wk, Wv, Wo);              // launch 1

    dim3 gqkv(24, 16);
    qkv_gemm<<<gqkv, 128, GSM>>>(kout, vout);                     // launch 2

    dim3 ga(T_ / 128, NH, B_);                                    // (8,16,2)
    attn_h<<<ga, 256, AHSM>>>();                                  // launch 3 (profiled)

    dim3 go(16, 16);
    o_gemm<<<go, 128, GSM>>>(out);                                // launch 4
}